// round 6
// baseline (speedup 1.0000x reference)
#include <cuda_runtime.h>
#include <cuda_bf16.h>
#include <cstdint>

#define CDIM 128
#define RNUM 7
#define TNUM 4
#define MAXN 100000
#define MAXE 2000000
#define NPH  (RNUM + TNUM)           /* 11 phases */
#define NCHK 22
#define SROW 144                     /* padded smem row stride bytes */
#define ATB  (128 * SROW)            /* 18432 B per chunk buffer */
#define SM_B (8 * ATB)               /* B buffer after 2 A stages: 147456 */
#define SM_TOT (SM_B + 65536)        /* 212992 */

// ---------------- device scratch ----------------
__device__ int  g_cnt[MAXN * RNUM];
__device__ int  g_off[MAXN * RNUM];
__device__ int  g_cur[MAXN * RNUM];
__device__ int2 g_offcnt[MAXN * RNUM];
__device__ int  g_bsum[1024];
__device__ int  g_esrc[MAXE];
// B fragments: [chunk][j(8)][s(4)][h(2)][lane(32)] uint4
__device__ __align__(16) uint4 g_Bf[NCHK * 8 * 4 * 2 * 32];

// ---------------- helpers ----------------
__device__ __forceinline__ uint32_t smem_u32(const void* p) {
    uint32_t a;
    asm("{ .reg .u64 t; cvta.to.shared.u64 t, %1; cvt.u32.u64 %0, t; }" : "=r"(a) : "l"(p));
    return a;
}
__device__ __forceinline__ void bar_sync(int id, int cnt) {
    asm volatile("bar.sync %0, %1;" :: "r"(id), "r"(cnt) : "memory");
}
__device__ __forceinline__ void bar_arrive(int id, int cnt) {
    asm volatile("bar.arrive %0, %1;" :: "r"(id), "r"(cnt) : "memory");
}
__device__ __forceinline__ void ldmat_x4(uint32_t addr, uint32_t* r) {
    asm volatile("ldmatrix.sync.aligned.m8n8.x4.shared.b16 {%0,%1,%2,%3}, [%4];"
                 : "=r"(r[0]), "=r"(r[1]), "=r"(r[2]), "=r"(r[3]) : "r"(addr));
}
__device__ __forceinline__ void mma4(float* d, const uint32_t* a, uint32_t b0, uint32_t b1) {
    asm volatile("mma.sync.aligned.m16n8k16.row.col.f32.bf16.bf16.f32 "
                 "{%0,%1,%2,%3}, {%4,%5,%6,%7}, {%8,%9}, {%0,%1,%2,%3};"
                 : "+f"(d[0]), "+f"(d[1]), "+f"(d[2]), "+f"(d[3])
                 : "r"(a[0]), "r"(a[1]), "r"(a[2]), "r"(a[3]), "r"(b0), "r"(b1));
}
__device__ __forceinline__ uint32_t packbf(float a, float b) {
    __nv_bfloat16 h0 = __float2bfloat16(a), h1 = __float2bfloat16(b);
    return (uint32_t)__bfloat16_as_ushort(h0) | ((uint32_t)__bfloat16_as_ushort(h1) << 16);
}
__device__ __forceinline__ uint4 lds128(uint32_t addr) {
    uint4 v;
    asm volatile("ld.shared.v4.b32 {%0,%1,%2,%3}, [%4];"
                 : "=r"(v.x), "=r"(v.y), "=r"(v.z), "=r"(v.w) : "r"(addr));
    return v;
}
// store one float4 (4 k-values) of row m as hi/lo bf16 into A stage buffers
__device__ __forceinline__ void storeA(uint32_t sbase, int m, int lane, float4 v) {
    int chunk = lane >> 4;
    uint32_t boff = (uint32_t)m * SROW + (lane & 15) * 8;
    uint32_t hp0 = packbf(v.x, v.y), hp1 = packbf(v.z, v.w);
    float rx = v.x - __bfloat162float(__float2bfloat16(v.x));
    float ry = v.y - __bfloat162float(__float2bfloat16(v.y));
    float rz = v.z - __bfloat162float(__float2bfloat16(v.z));
    float rw = v.w - __bfloat162float(__float2bfloat16(v.w));
    uint32_t lp0 = packbf(rx, ry), lp1 = packbf(rz, rw);
    asm volatile("st.shared.v2.b32 [%0], {%1,%2};"
                 :: "r"(sbase + (chunk * 2 + 0) * ATB + boff), "r"(hp0), "r"(hp1) : "memory");
    asm volatile("st.shared.v2.b32 [%0], {%1,%2};"
                 :: "r"(sbase + (chunk * 2 + 1) * ATB + boff), "r"(lp0), "r"(lp1) : "memory");
}

// ---------------- prologue kernels ----------------
__global__ void k_zero(int nseg) {
    int i = blockIdx.x * blockDim.x + threadIdx.x;
    if (i < nseg) g_cnt[i] = 0;
}
__global__ void k_count(const int* __restrict__ ei, const int* __restrict__ et, int E) {
    int e = blockIdx.x * blockDim.x + threadIdx.x;
    if (e >= E) return;
    atomicAdd(&g_cnt[ei[E + e] * RNUM + et[e]], 1);
}
__global__ void k_scan1(int nseg) {
    __shared__ int wsum[8];
    int tid = threadIdx.x;
    int base = blockIdx.x * 1024 + tid * 4;
    int v0 = 0, v1 = 0, v2 = 0, v3 = 0;
    if (base + 0 < nseg) v0 = g_cnt[base + 0];
    if (base + 1 < nseg) v1 = g_cnt[base + 1];
    if (base + 2 < nseg) v2 = g_cnt[base + 2];
    if (base + 3 < nseg) v3 = g_cnt[base + 3];
    int tot = v0 + v1 + v2 + v3;
    int lane = tid & 31, wid = tid >> 5;
    int inc = tot;
#pragma unroll
    for (int d = 1; d < 32; d <<= 1) {
        int t = __shfl_up_sync(0xffffffff, inc, d);
        if (lane >= d) inc += t;
    }
    if (lane == 31) wsum[wid] = inc;
    __syncthreads();
    if (wid == 0) {
        int w = (lane < 8) ? wsum[lane] : 0;
#pragma unroll
        for (int d = 1; d < 8; d <<= 1) {
            int t = __shfl_up_sync(0xffffffff, w, d);
            if (lane >= d) w += t;
        }
        if (lane < 8) wsum[lane] = w;
    }
    __syncthreads();
    int excl = inc - tot + (wid ? wsum[wid - 1] : 0);
    if (base + 0 < nseg) g_off[base + 0] = excl;
    if (base + 1 < nseg) g_off[base + 1] = excl + v0;
    if (base + 2 < nseg) g_off[base + 2] = excl + v0 + v1;
    if (base + 3 < nseg) g_off[base + 3] = excl + v0 + v1 + v2;
    if (tid == 255) g_bsum[blockIdx.x] = wsum[7];
}
__global__ void k_scan2(int nb) {
    __shared__ int sm[1024];
    int tid = threadIdx.x;
    int v = (tid < nb) ? g_bsum[tid] : 0;
    sm[tid] = v;
    __syncthreads();
    for (int d = 1; d < 1024; d <<= 1) {
        int t = (tid >= d) ? sm[tid - d] : 0;
        __syncthreads();
        sm[tid] += t;
        __syncthreads();
    }
    if (tid < nb) g_bsum[tid] = sm[tid] - v;
}
__global__ void k_scan3(int nseg) {
    int i = blockIdx.x * blockDim.x + threadIdx.x;
    if (i < nseg) {
        int v = g_off[i] + g_bsum[i >> 10];
        g_cur[i] = v;
        g_offcnt[i] = make_int2(v, g_cnt[i]);
    }
}
__global__ void k_scatter(const int* __restrict__ ei, const int* __restrict__ et, int E) {
    int e = blockIdx.x * blockDim.x + threadIdx.x;
    if (e >= E) return;
    int s = ei[E + e] * RNUM + et[e];
    int p = atomicAdd(&g_cur[s], 1);
    g_esrc[p] = ei[e];
}
__global__ void k_buildBf(const float* __restrict__ rel_w,
                          const float* __restrict__ root_w) {
    int idx = blockIdx.x * blockDim.x + threadIdx.x;
    if (idx >= NCHK * 8 * 4 * 32) return;
    int lane = idx & 31;
    int s = (idx >> 5) & 3;
    int j = (idx >> 7) & 7;
    int chunk = idx >> 10;
    uint32_t hi[4], lo[4];
#pragma unroll
    for (int q = 0; q < 4; q++) {
        int n = j * 16 + ((q & 2) ? 8 : 0) + (lane >> 2);
        int kk = s * 16 + ((q & 1) ? 8 : 0) + 2 * (lane & 3);
        float w0, w1;
        if (chunk < 14) {
            int r = chunk >> 1, kb = (chunk & 1) * 64;
            const float* p = rel_w + ((size_t)(r * CDIM + n)) * CDIM + kb + kk;
            w0 = p[0]; w1 = p[1];
        } else {
            int rc = chunk - 14;
            int t = rc >> 1, kb = (rc & 1) * 64;
            const float* p = root_w + ((size_t)(t * CDIM + n)) * CDIM + kb + kk;
            w0 = p[0]; w1 = p[1];
        }
        __nv_bfloat16 h0 = __float2bfloat16(w0), h1 = __float2bfloat16(w1);
        float r0 = w0 - __bfloat162float(h0), r1 = w1 - __bfloat162float(h1);
        hi[q] = (uint32_t)__bfloat16_as_ushort(h0) | ((uint32_t)__bfloat16_as_ushort(h1) << 16);
        lo[q] = packbf(r0, r1);
    }
    size_t base = ((((size_t)chunk * 8 + j) * 4 + s) * 2) * 32 + lane;
    g_Bf[base]      = make_uint4(hi[0], hi[1], hi[2], hi[3]);
    g_Bf[base + 32] = make_uint4(lo[0], lo[1], lo[2], lo[3]);
}

// ---------------- fused kernel: warp-specialized pipeline -------------------
// warps 0-7: mma consumers (warp w -> rows w*16..w*16+15, all 128 cols)
// warps 8-15: gather producers (warp w-8 -> rows (w-8)*16..+15)
// barriers: FULL(st)=1+st, EMPTY(st)=3+st (count 512); consumer-only: 5,6 (256)
__global__ __launch_bounds__(512, 1) void k_fused(const float* __restrict__ x,
                                                  const int* __restrict__ tnt,
                                                  const float* __restrict__ root_b,
                                                  float* __restrict__ out, int Nn) {
    extern __shared__ char smem[];
    const uint32_t sb = smem_u32(smem);
    const int tid = threadIdx.x, wid = tid >> 5, lane = tid & 31;
    const int row0 = blockIdx.x * 128;
    const float4* x4 = reinterpret_cast<const float4*>(x);

    if (wid >= 8) {
        // ================= PRODUCER =================
        const int pw = wid - 8;
        for (int p = 0; p < NPH; ++p) {
            const int st = p & 1;
            if (p >= 2) bar_sync(3 + st, 512);           // wait stage empty
            const uint32_t abase = sb + st * 4 * ATB;
            if (p < RNUM) {
                const int r = p;
#pragma unroll 1
                for (int b = 0; b < 4; b++) {
                    int oc_o[4], oc_c[4];
                    int4 sr[4];
#pragma unroll
                    for (int i = 0; i < 4; i++) {
                        int dst = row0 + pw * 16 + b * 4 + i;
                        int2 oc = (dst < Nn) ? g_offcnt[dst * RNUM + r] : make_int2(0, 0);
                        oc_o[i] = oc.x; oc_c[i] = oc.y;
                    }
#pragma unroll
                    for (int i = 0; i < 4; i++) {
                        sr[i].x = (0 < oc_c[i]) ? g_esrc[oc_o[i] + 0] : 0;
                        sr[i].y = (1 < oc_c[i]) ? g_esrc[oc_o[i] + 1] : 0;
                        sr[i].z = (2 < oc_c[i]) ? g_esrc[oc_o[i] + 2] : 0;
                        sr[i].w = (3 < oc_c[i]) ? g_esrc[oc_o[i] + 3] : 0;
                    }
#pragma unroll
                    for (int i = 0; i < 4; i++) {
                        float4 a = make_float4(0.f, 0.f, 0.f, 0.f);
                        const int c = oc_c[i];
                        if (c > 0) { float4 u = x4[(size_t)sr[i].x * 32 + lane];
                                     a.x += u.x; a.y += u.y; a.z += u.z; a.w += u.w; }
                        if (c > 1) { float4 u = x4[(size_t)sr[i].y * 32 + lane];
                                     a.x += u.x; a.y += u.y; a.z += u.z; a.w += u.w; }
                        if (c > 2) { float4 u = x4[(size_t)sr[i].z * 32 + lane];
                                     a.x += u.x; a.y += u.y; a.z += u.z; a.w += u.w; }
                        if (c > 3) { float4 u = x4[(size_t)sr[i].w * 32 + lane];
                                     a.x += u.x; a.y += u.y; a.z += u.z; a.w += u.w; }
                        for (int j = 4; j < c; j++) {
                            float4 u = x4[(size_t)g_esrc[oc_o[i] + j] * 32 + lane];
                            a.x += u.x; a.y += u.y; a.z += u.z; a.w += u.w;
                        }
                        const float inv = 1.f / fmaxf((float)c, 1.f);
                        a.x *= inv; a.y *= inv; a.z *= inv; a.w *= inv;
                        storeA(abase, pw * 16 + b * 4 + i, lane, a);
                    }
                }
            } else {
                const int t = p - RNUM;
#pragma unroll 1
                for (int i = 0; i < 16; i++) {
                    const int m = pw * 16 + i;
                    const int dst = row0 + m;
                    float4 v = make_float4(0.f, 0.f, 0.f, 0.f);
                    if (dst < Nn && tnt[dst] == t) v = x4[(size_t)dst * 32 + lane];
                    storeA(abase, m, lane, v);
                }
            }
            bar_arrive(1 + st, 512);                     // stage full
        }
        return;
    }

    // ================= CONSUMER =================
    const int quad = lane >> 3, lrow = lane & 7;
    const int a_roff = ((quad & 1) * 8 + lrow) * SROW + ((quad >> 1) * 8) * 2;
    const uint32_t sbB = sb + SM_B;

    float acc[16][4];
#pragma unroll
    for (int j = 0; j < 16; j++)
#pragma unroll
        for (int q = 0; q < 4; q++) acc[j][q] = 0.f;

    for (int p = 0; p < NPH; ++p) {
        const int st = p & 1;
        bar_sync(1 + st, 512);                           // wait stage full
        // ---- cooperative B copy: 4096 uint4 over 256 threads ----
        {
            const uint4* src = g_Bf + (size_t)p * 4096;
            uint4* d = reinterpret_cast<uint4*>(smem + SM_B);
#pragma unroll
            for (int i = 0; i < 16; i++) d[tid + i * 256] = src[tid + i * 256];
        }
        bar_sync(5, 256);
        // ---- GEMM ----
        const uint32_t aHi0 = sb + (st * 4 + 0) * ATB + (uint32_t)wid * 16 * SROW + a_roff;
#pragma unroll
        for (int cc = 0; cc < 2; cc++) {
#pragma unroll
            for (int s = 0; s < 4; s++) {
                uint32_t ah[4], al[4];
                const uint32_t abase = aHi0 + cc * 2 * ATB + s * 32;
                ldmat_x4(abase, ah);
                ldmat_x4(abase + ATB, al);
#pragma unroll
                for (int j = 0; j < 8; j++) {
                    const uint32_t boff = sbB + ((((cc * 8 + j) * 4 + s) * 64) + lane) * 16;
                    uint4 BH = lds128(boff);
                    uint4 BL = lds128(boff + 512);
                    mma4(acc[2 * j],     ah, BH.x, BH.y);
                    mma4(acc[2 * j + 1], ah, BH.z, BH.w);
                    mma4(acc[2 * j],     ah, BL.x, BL.y);
                    mma4(acc[2 * j + 1], ah, BL.z, BL.w);
                    mma4(acc[2 * j],     al, BH.x, BH.y);
                    mma4(acc[2 * j + 1], al, BH.z, BH.w);
                }
            }
        }
        bar_sync(6, 256);                                // all consumers done with B
        bar_arrive(3 + st, 512);                         // stage empty
    }

    // ---- epilogue ----
    const int g = lane >> 2, tig = lane & 3;
    const int r1 = row0 + wid * 16 + g;
    const int r2 = r1 + 8;
    const int t1 = (r1 < Nn) ? tnt[r1] : 0;
    const int t2 = (r2 < Nn) ? tnt[r2] : 0;
#pragma unroll
    for (int nt = 0; nt < 16; nt++) {
        const int col = nt * 8 + tig * 2;
        if (r1 < Nn) {
            float2 b1 = *reinterpret_cast<const float2*>(root_b + t1 * CDIM + col);
            *reinterpret_cast<float2*>(out + (size_t)r1 * CDIM + col) =
                make_float2(acc[nt][0] + b1.x, acc[nt][1] + b1.y);
        }
        if (r2 < Nn) {
            float2 b2 = *reinterpret_cast<const float2*>(root_b + t2 * CDIM + col);
            *reinterpret_cast<float2*>(out + (size_t)r2 * CDIM + col) =
                make_float2(acc[nt][2] + b2.x, acc[nt][3] + b2.y);
        }
    }
}

// ---------------------------------------------------------------------------
extern "C" void kernel_launch(void* const* d_in, const int* in_sizes, int n_in,
                              void* d_out, int out_size) {
    const float* x      = (const float*)d_in[0];
    const int*   ei     = (const int*)d_in[1];
    const int*   et     = (const int*)d_in[2];
    const int*   tnt    = (const int*)d_in[3];
    const float* rel_w  = (const float*)d_in[4];
    const float* root_w = (const float*)d_in[5];
    const float* root_b = (const float*)d_in[6];
    float* out = (float*)d_out;

    int E  = in_sizes[2];
    int Nn = in_sizes[3];
    int nseg = Nn * RNUM;
    int nb = (nseg + 1023) / 1024;

    cudaFuncSetAttribute(k_fused, cudaFuncAttributeMaxDynamicSharedMemorySize, SM_TOT);

    k_zero<<<(nseg + 255) / 256, 256>>>(nseg);
    k_count<<<(E + 255) / 256, 256>>>(ei, et, E);
    k_scan1<<<nb, 256>>>(nseg);
    k_scan2<<<1, 1024>>>(nb);
    k_scan3<<<(nseg + 255) / 256, 256>>>(nseg);
    k_scatter<<<(E + 255) / 256, 256>>>(ei, et, E);
    k_buildBf<<<(NCHK * 8 * 4 * 32 + 255) / 256, 256>>>(rel_w, root_w);
    k_fused<<<(Nn + 127) / 128, 512, SM_TOT>>>(x, tnt, root_b, out, Nn);
}

// round 7
// speedup vs baseline: 1.1662x; 1.1662x over previous
#include <cuda_runtime.h>
#include <cuda_bf16.h>
#include <cstdint>

#define CDIM 128
#define RNUM 7
#define TNUM 4
#define MAXN 100000
#define MAXE 2000000
#define NPH  (RNUM + TNUM)           /* 11 phases */
#define NCHK 22
#define SROW 144                     /* padded smem row stride bytes */
#define ATB  (128 * SROW)            /* 18432 B per chunk buffer */
#define SM_B (4 * ATB)               /* B stages start after A: 73728 */
#define BSTAGE 65536                 /* one B stage: 64 KB */
#define SM_TOT (SM_B + 2 * BSTAGE)   /* 204800 */

// ---------------- device scratch ----------------
__device__ int  g_cnt[MAXN * RNUM];
__device__ int  g_off[MAXN * RNUM];
__device__ int  g_cur[MAXN * RNUM];
__device__ int2 g_offcnt[MAXN * RNUM];
__device__ int  g_bsum[1024];
__device__ int  g_esrc[MAXE];
// B fragments: [chunk][j(8)][s(4)][h(2)][lane(32)] uint4
__device__ __align__(16) uint4 g_Bf[NCHK * 8 * 4 * 2 * 32];

// ---------------- helpers ----------------
__device__ __forceinline__ uint32_t smem_u32(const void* p) {
    uint32_t a;
    asm("{ .reg .u64 t; cvta.to.shared.u64 t, %1; cvt.u32.u64 %0, t; }" : "=r"(a) : "l"(p));
    return a;
}
__device__ __forceinline__ void ldmat_x4(uint32_t addr, uint32_t* r) {
    asm volatile("ldmatrix.sync.aligned.m8n8.x4.shared.b16 {%0,%1,%2,%3}, [%4];"
                 : "=r"(r[0]), "=r"(r[1]), "=r"(r[2]), "=r"(r[3]) : "r"(addr));
}
__device__ __forceinline__ void mma4(float* d, const uint32_t* a, uint32_t b0, uint32_t b1) {
    asm volatile("mma.sync.aligned.m16n8k16.row.col.f32.bf16.bf16.f32 "
                 "{%0,%1,%2,%3}, {%4,%5,%6,%7}, {%8,%9}, {%0,%1,%2,%3};"
                 : "+f"(d[0]), "+f"(d[1]), "+f"(d[2]), "+f"(d[3])
                 : "r"(a[0]), "r"(a[1]), "r"(a[2]), "r"(a[3]), "r"(b0), "r"(b1));
}
__device__ __forceinline__ uint32_t packbf(float a, float b) {
    __nv_bfloat16 h0 = __float2bfloat16(a), h1 = __float2bfloat16(b);
    return (uint32_t)__bfloat16_as_ushort(h0) | ((uint32_t)__bfloat16_as_ushort(h1) << 16);
}
__device__ __forceinline__ uint4 lds128(uint32_t addr) {
    uint4 v;
    asm volatile("ld.shared.v4.b32 {%0,%1,%2,%3}, [%4];"
                 : "=r"(v.x), "=r"(v.y), "=r"(v.z), "=r"(v.w) : "r"(addr));
    return v;
}
__device__ __forceinline__ void cp16(uint32_t s, const void* g) {
    asm volatile("cp.async.cg.shared.global [%0], [%1], 16;" :: "r"(s), "l"(g));
}
#define CP_COMMIT() asm volatile("cp.async.commit_group;" ::: "memory")
#define CP_WAIT1()  asm volatile("cp.async.wait_group 1;" ::: "memory")

// store one float4 (4 k-values) of row m as hi/lo bf16 into A buffers
__device__ __forceinline__ void storeA(uint32_t sbase, int m, int lane, float4 v) {
    int chunk = lane >> 4;
    uint32_t boff = (uint32_t)m * SROW + (lane & 15) * 8;
    uint32_t hp0 = packbf(v.x, v.y), hp1 = packbf(v.z, v.w);
    float rx = v.x - __bfloat162float(__float2bfloat16(v.x));
    float ry = v.y - __bfloat162float(__float2bfloat16(v.y));
    float rz = v.z - __bfloat162float(__float2bfloat16(v.z));
    float rw = v.w - __bfloat162float(__float2bfloat16(v.w));
    uint32_t lp0 = packbf(rx, ry), lp1 = packbf(rz, rw);
    asm volatile("st.shared.v2.b32 [%0], {%1,%2};"
                 :: "r"(sbase + (chunk * 2 + 0) * ATB + boff), "r"(hp0), "r"(hp1) : "memory");
    asm volatile("st.shared.v2.b32 [%0], {%1,%2};"
                 :: "r"(sbase + (chunk * 2 + 1) * ATB + boff), "r"(lp0), "r"(lp1) : "memory");
}

// ---------------- prologue kernels ----------------
__global__ void k_zero(int nseg) {
    int i = blockIdx.x * blockDim.x + threadIdx.x;
    if (i < nseg) g_cnt[i] = 0;
}
__global__ void k_count(const int* __restrict__ ei, const int* __restrict__ et, int E) {
    int e = blockIdx.x * blockDim.x + threadIdx.x;
    if (e >= E) return;
    atomicAdd(&g_cnt[ei[E + e] * RNUM + et[e]], 1);
}
__global__ void k_scan1(int nseg) {
    __shared__ int wsum[8];
    int tid = threadIdx.x;
    int base = blockIdx.x * 1024 + tid * 4;
    int v0 = 0, v1 = 0, v2 = 0, v3 = 0;
    if (base + 0 < nseg) v0 = g_cnt[base + 0];
    if (base + 1 < nseg) v1 = g_cnt[base + 1];
    if (base + 2 < nseg) v2 = g_cnt[base + 2];
    if (base + 3 < nseg) v3 = g_cnt[base + 3];
    int tot = v0 + v1 + v2 + v3;
    int lane = tid & 31, wid = tid >> 5;
    int inc = tot;
#pragma unroll
    for (int d = 1; d < 32; d <<= 1) {
        int t = __shfl_up_sync(0xffffffff, inc, d);
        if (lane >= d) inc += t;
    }
    if (lane == 31) wsum[wid] = inc;
    __syncthreads();
    if (wid == 0) {
        int w = (lane < 8) ? wsum[lane] : 0;
#pragma unroll
        for (int d = 1; d < 8; d <<= 1) {
            int t = __shfl_up_sync(0xffffffff, w, d);
            if (lane >= d) w += t;
        }
        if (lane < 8) wsum[lane] = w;
    }
    __syncthreads();
    int excl = inc - tot + (wid ? wsum[wid - 1] : 0);
    if (base + 0 < nseg) g_off[base + 0] = excl;
    if (base + 1 < nseg) g_off[base + 1] = excl + v0;
    if (base + 2 < nseg) g_off[base + 2] = excl + v0 + v1;
    if (base + 3 < nseg) g_off[base + 3] = excl + v0 + v1 + v2;
    if (tid == 255) g_bsum[blockIdx.x] = wsum[7];
}
__global__ void k_scan2(int nb) {
    __shared__ int sm[1024];
    int tid = threadIdx.x;
    int v = (tid < nb) ? g_bsum[tid] : 0;
    sm[tid] = v;
    __syncthreads();
    for (int d = 1; d < 1024; d <<= 1) {
        int t = (tid >= d) ? sm[tid - d] : 0;
        __syncthreads();
        sm[tid] += t;
        __syncthreads();
    }
    if (tid < nb) g_bsum[tid] = sm[tid] - v;
}
__global__ void k_scan3(int nseg) {
    int i = blockIdx.x * blockDim.x + threadIdx.x;
    if (i < nseg) {
        int v = g_off[i] + g_bsum[i >> 10];
        g_cur[i] = v;
        g_offcnt[i] = make_int2(v, g_cnt[i]);
    }
}
__global__ void k_scatter(const int* __restrict__ ei, const int* __restrict__ et, int E) {
    int e = blockIdx.x * blockDim.x + threadIdx.x;
    if (e >= E) return;
    int s = ei[E + e] * RNUM + et[e];
    int p = atomicAdd(&g_cur[s], 1);
    g_esrc[p] = ei[e];
}
__global__ void k_buildBf(const float* __restrict__ rel_w,
                          const float* __restrict__ root_w) {
    int idx = blockIdx.x * blockDim.x + threadIdx.x;
    if (idx >= NCHK * 8 * 4 * 32) return;
    int lane = idx & 31;
    int s = (idx >> 5) & 3;
    int j = (idx >> 7) & 7;
    int chunk = idx >> 10;
    uint32_t hi[4], lo[4];
#pragma unroll
    for (int q = 0; q < 4; q++) {
        int n = j * 16 + ((q & 2) ? 8 : 0) + (lane >> 2);
        int kk = s * 16 + ((q & 1) ? 8 : 0) + 2 * (lane & 3);
        float w0, w1;
        if (chunk < 14) {
            int r = chunk >> 1, kb = (chunk & 1) * 64;
            const float* p = rel_w + ((size_t)(r * CDIM + n)) * CDIM + kb + kk;
            w0 = p[0]; w1 = p[1];
        } else {
            int rc = chunk - 14;
            int t = rc >> 1, kb = (rc & 1) * 64;
            const float* p = root_w + ((size_t)(t * CDIM + n)) * CDIM + kb + kk;
            w0 = p[0]; w1 = p[1];
        }
        __nv_bfloat16 h0 = __float2bfloat16(w0), h1 = __float2bfloat16(w1);
        float r0 = w0 - __bfloat162float(h0), r1 = w1 - __bfloat162float(h1);
        hi[q] = (uint32_t)__bfloat16_as_ushort(h0) | ((uint32_t)__bfloat16_as_ushort(h1) << 16);
        lo[q] = packbf(r0, r1);
    }
    size_t base = ((((size_t)chunk * 8 + j) * 4 + s) * 2) * 32 + lane;
    g_Bf[base]      = make_uint4(hi[0], hi[1], hi[2], hi[3]);
    g_Bf[base + 32] = make_uint4(lo[0], lo[1], lo[2], lo[3]);
}

// ---------------- fused: gather + GEMM, B double-buffered via cp.async ------
__global__ __launch_bounds__(512, 1) void k_fused(const float* __restrict__ x,
                                                  const int* __restrict__ tnt,
                                                  const float* __restrict__ root_b,
                                                  float* __restrict__ out, int Nn) {
    extern __shared__ char smem[];
    const uint32_t sb = smem_u32(smem);
    const int tid = threadIdx.x, wid = tid >> 5, lane = tid & 31;
    const int row0 = blockIdx.x * 128;
    const int wm0 = (wid & 7) * 16;
    const int jbase = (wid >> 3) * 4;
    const int wn0 = jbase * 16;
    const int quad = lane >> 3, lrow = lane & 7;
    const int a_roff = ((quad & 1) * 8 + lrow) * SROW + ((quad >> 1) * 8) * 2;
    const float4* x4 = reinterpret_cast<const float4*>(x);

    float acc[8][4];
#pragma unroll
    for (int j = 0; j < 8; j++)
#pragma unroll
        for (int q = 0; q < 4; q++) acc[j][q] = 0.f;

    // prefetch B phase 0
    {
        const uint4* src = g_Bf;
        const uint32_t d0 = sb + SM_B;
#pragma unroll
        for (int i = 0; i < 8; i++)
            cp16(d0 + (tid + i * 512) * 16, src + tid + i * 512);
        CP_COMMIT();
    }

    for (int phase = 0; phase < NPH; ++phase) {
        __syncthreads();   // prior mma done reading A + prior B stage free
        // ---- prefetch B for next phase ----
        if (phase + 1 < NPH) {
            const uint4* src = g_Bf + (size_t)(phase + 1) * 4096;
            const uint32_t d0 = sb + SM_B + ((phase + 1) & 1) * BSTAGE;
#pragma unroll
            for (int i = 0; i < 8; i++)
                cp16(d0 + (tid + i * 512) * 16, src + tid + i * 512);
        }
        CP_COMMIT();
        // ---- build A (8 rows per warp) ----
#pragma unroll 1
        for (int i = 0; i < 8; i++) {
            int m = wid * 8 + i;
            int dst = row0 + m;
            float4 v = make_float4(0.f, 0.f, 0.f, 0.f);
            if (dst < Nn) {
                if (phase < RNUM) {
                    int2 oc = g_offcnt[dst * RNUM + phase];
                    int o0 = oc.x, c = oc.y;
                    float4 a0 = make_float4(0.f, 0.f, 0.f, 0.f);
                    float4 a1 = make_float4(0.f, 0.f, 0.f, 0.f);
                    int j = 0;
                    for (; j + 2 <= c; j += 2) {
                        int s0 = g_esrc[o0 + j], s1 = g_esrc[o0 + j + 1];
                        float4 u0 = x4[(size_t)s0 * 32 + lane];
                        float4 u1 = x4[(size_t)s1 * 32 + lane];
                        a0.x += u0.x; a0.y += u0.y; a0.z += u0.z; a0.w += u0.w;
                        a1.x += u1.x; a1.y += u1.y; a1.z += u1.z; a1.w += u1.w;
                    }
                    if (j < c) {
                        float4 u = x4[(size_t)g_esrc[o0 + j] * 32 + lane];
                        a0.x += u.x; a0.y += u.y; a0.z += u.z; a0.w += u.w;
                    }
                    float inv = 1.f / fmaxf((float)c, 1.f);
                    v.x = (a0.x + a1.x) * inv; v.y = (a0.y + a1.y) * inv;
                    v.z = (a0.z + a1.z) * inv; v.w = (a0.w + a1.w) * inv;
                } else {
                    int t = phase - RNUM;
                    if (tnt[dst] == t) v = x4[(size_t)dst * 32 + lane];
                }
            }
            storeA(sb, m, lane, v);
        }
        CP_WAIT1();        // current phase's B landed (next-phase group may remain)
        __syncthreads();
        // ---- GEMM: 2 K-chunks of 64, B from SMEM ----
        const uint32_t sbB = sb + SM_B + (phase & 1) * BSTAGE;
#pragma unroll
        for (int cc = 0; cc < 2; cc++) {
#pragma unroll
            for (int s = 0; s < 4; s++) {
                uint32_t ah[4], al[4];
                const uint32_t abase = (uint32_t)wm0 * SROW + s * 32 + a_roff;
                ldmat_x4(sb + (cc * 2 + 0) * ATB + abase, ah);
                ldmat_x4(sb + (cc * 2 + 1) * ATB + abase, al);
#pragma unroll
                for (int jp = 0; jp < 4; jp++) {
                    const uint32_t boff = sbB +
                        ((((uint32_t)(cc * 8 + jbase + jp) * 4 + s) * 2) * 32 + lane) * 16;
                    uint4 BH = lds128(boff);
                    uint4 BL = lds128(boff + 512);
                    mma4(acc[2 * jp],     ah, BH.x, BH.y);
                    mma4(acc[2 * jp + 1], ah, BH.z, BH.w);
                    mma4(acc[2 * jp],     ah, BL.x, BL.y);
                    mma4(acc[2 * jp + 1], ah, BL.z, BL.w);
                    mma4(acc[2 * jp],     al, BH.x, BH.y);
                    mma4(acc[2 * jp + 1], al, BH.z, BH.w);
                }
            }
        }
    }

    // ---- epilogue: + root_b[tnt], single store ----
    const int g = lane >> 2, tig = lane & 3;
    const int r1 = row0 + wm0 + g;
    const int r2 = r1 + 8;
    const int t1 = (r1 < Nn) ? tnt[r1] : 0;
    const int t2 = (r2 < Nn) ? tnt[r2] : 0;
#pragma unroll
    for (int nt = 0; nt < 8; nt++) {
        const int col = wn0 + nt * 8 + tig * 2;
        if (r1 < Nn) {
            float2 b1 = *reinterpret_cast<const float2*>(root_b + t1 * CDIM + col);
            *reinterpret_cast<float2*>(out + (size_t)r1 * CDIM + col) =
                make_float2(acc[nt][0] + b1.x, acc[nt][1] + b1.y);
        }
        if (r2 < Nn) {
            float2 b2 = *reinterpret_cast<const float2*>(root_b + t2 * CDIM + col);
            *reinterpret_cast<float2*>(out + (size_t)r2 * CDIM + col) =
                make_float2(acc[nt][2] + b2.x, acc[nt][3] + b2.y);
        }
    }
}

// ---------------------------------------------------------------------------
extern "C" void kernel_launch(void* const* d_in, const int* in_sizes, int n_in,
                              void* d_out, int out_size) {
    const float* x      = (const float*)d_in[0];
    const int*   ei     = (const int*)d_in[1];
    const int*   et     = (const int*)d_in[2];
    const int*   tnt    = (const int*)d_in[3];
    const float* rel_w  = (const float*)d_in[4];
    const float* root_w = (const float*)d_in[5];
    const float* root_b = (const float*)d_in[6];
    float* out = (float*)d_out;

    int E  = in_sizes[2];
    int Nn = in_sizes[3];
    int nseg = Nn * RNUM;
    int nb = (nseg + 1023) / 1024;

    cudaFuncSetAttribute(k_fused, cudaFuncAttributeMaxDynamicSharedMemorySize, SM_TOT);

    k_zero<<<(nseg + 255) / 256, 256>>>(nseg);
    k_count<<<(E + 255) / 256, 256>>>(ei, et, E);
    k_scan1<<<nb, 256>>>(nseg);
    k_scan2<<<1, 1024>>>(nb);
    k_scan3<<<(nseg + 255) / 256, 256>>>(nseg);
    k_scatter<<<(E + 255) / 256, 256>>>(ei, et, E);
    k_buildBf<<<(NCHK * 8 * 4 * 32 + 255) / 256, 256>>>(rel_w, root_w);
    k_fused<<<(Nn + 127) / 128, 512, SM_TOT>>>(x, tnt, root_b, out, Nn);
}

// round 8
// speedup vs baseline: 1.3671x; 1.1722x over previous
#include <cuda_runtime.h>
#include <cuda_bf16.h>
#include <cstdint>

#define CDIM 128
#define RNUM 7
#define TNUM 4
#define MAXN 100000
#define MAXE 2000000
#define NPH  (RNUM + TNUM)           /* 11 phases */
#define NCHK 22
#define SROW 144                     /* padded smem row stride bytes */
#define ATB  (128 * SROW)            /* 18432 B per chunk buffer */
#define SM_B (4 * ATB)               /* B stages start after A: 73728 */
#define BSTAGE 65536                 /* one B stage: 64 KB */
#define SM_TOT (SM_B + 2 * BSTAGE)   /* 204800 */

// ---------------- device scratch ----------------
__device__ int  g_cnt[MAXN * RNUM];
__device__ int  g_off[MAXN * RNUM];
__device__ int  g_cur[MAXN * RNUM];
__device__ int2 g_offcnt[MAXN * RNUM];
__device__ int  g_bsum[1024];
__device__ int  g_esrc[MAXE];
// B fragments: [chunk][j(8)][s(4)][h(2)][lane(32)] uint4
__device__ __align__(16) uint4 g_Bf[NCHK * 8 * 4 * 2 * 32];

// ---------------- helpers ----------------
__device__ __forceinline__ uint32_t smem_u32(const void* p) {
    uint32_t a;
    asm("{ .reg .u64 t; cvta.to.shared.u64 t, %1; cvt.u32.u64 %0, t; }" : "=r"(a) : "l"(p));
    return a;
}
__device__ __forceinline__ void ldmat_x4(uint32_t addr, uint32_t* r) {
    asm volatile("ldmatrix.sync.aligned.m8n8.x4.shared.b16 {%0,%1,%2,%3}, [%4];"
                 : "=r"(r[0]), "=r"(r[1]), "=r"(r[2]), "=r"(r[3]) : "r"(addr));
}
__device__ __forceinline__ void mma4(float* d, const uint32_t* a, uint32_t b0, uint32_t b1) {
    asm volatile("mma.sync.aligned.m16n8k16.row.col.f32.bf16.bf16.f32 "
                 "{%0,%1,%2,%3}, {%4,%5,%6,%7}, {%8,%9}, {%0,%1,%2,%3};"
                 : "+f"(d[0]), "+f"(d[1]), "+f"(d[2]), "+f"(d[3])
                 : "r"(a[0]), "r"(a[1]), "r"(a[2]), "r"(a[3]), "r"(b0), "r"(b1));
}
__device__ __forceinline__ uint32_t packbf(float a, float b) {
    __nv_bfloat16 h0 = __float2bfloat16(a), h1 = __float2bfloat16(b);
    return (uint32_t)__bfloat16_as_ushort(h0) | ((uint32_t)__bfloat16_as_ushort(h1) << 16);
}
__device__ __forceinline__ uint4 lds128(uint32_t addr) {
    uint4 v;
    asm volatile("ld.shared.v4.b32 {%0,%1,%2,%3}, [%4];"
                 : "=r"(v.x), "=r"(v.y), "=r"(v.z), "=r"(v.w) : "r"(addr));
    return v;
}
__device__ __forceinline__ void cp16(uint32_t s, const void* g) {
    asm volatile("cp.async.cg.shared.global [%0], [%1], 16;" :: "r"(s), "l"(g));
}
#define CP_COMMIT() asm volatile("cp.async.commit_group;" ::: "memory")
#define CP_WAIT1()  asm volatile("cp.async.wait_group 1;" ::: "memory")

// store one float4 (4 k-values) of row m as hi/lo bf16 into A buffers
__device__ __forceinline__ void storeA(uint32_t sbase, int m, int lane, float4 v) {
    int chunk = lane >> 4;
    uint32_t boff = (uint32_t)m * SROW + (lane & 15) * 8;
    uint32_t hp0 = packbf(v.x, v.y), hp1 = packbf(v.z, v.w);
    float rx = v.x - __bfloat162float(__float2bfloat16(v.x));
    float ry = v.y - __bfloat162float(__float2bfloat16(v.y));
    float rz = v.z - __bfloat162float(__float2bfloat16(v.z));
    float rw = v.w - __bfloat162float(__float2bfloat16(v.w));
    uint32_t lp0 = packbf(rx, ry), lp1 = packbf(rz, rw);
    asm volatile("st.shared.v2.b32 [%0], {%1,%2};"
                 :: "r"(sbase + (chunk * 2 + 0) * ATB + boff), "r"(hp0), "r"(hp1) : "memory");
    asm volatile("st.shared.v2.b32 [%0], {%1,%2};"
                 :: "r"(sbase + (chunk * 2 + 1) * ATB + boff), "r"(lp0), "r"(lp1) : "memory");
}

// ---------------- prologue kernels ----------------
__global__ void k_zero(int nseg) {
    int i = blockIdx.x * blockDim.x + threadIdx.x;
    if (i < nseg) g_cnt[i] = 0;
}
__global__ void k_count(const int* __restrict__ ei, const int* __restrict__ et, int E) {
    int e = blockIdx.x * blockDim.x + threadIdx.x;
    if (e >= E) return;
    atomicAdd(&g_cnt[ei[E + e] * RNUM + et[e]], 1);
}
__global__ void k_scan1(int nseg) {
    __shared__ int wsum[8];
    int tid = threadIdx.x;
    int base = blockIdx.x * 1024 + tid * 4;
    int v0 = 0, v1 = 0, v2 = 0, v3 = 0;
    if (base + 0 < nseg) v0 = g_cnt[base + 0];
    if (base + 1 < nseg) v1 = g_cnt[base + 1];
    if (base + 2 < nseg) v2 = g_cnt[base + 2];
    if (base + 3 < nseg) v3 = g_cnt[base + 3];
    int tot = v0 + v1 + v2 + v3;
    int lane = tid & 31, wid = tid >> 5;
    int inc = tot;
#pragma unroll
    for (int d = 1; d < 32; d <<= 1) {
        int t = __shfl_up_sync(0xffffffff, inc, d);
        if (lane >= d) inc += t;
    }
    if (lane == 31) wsum[wid] = inc;
    __syncthreads();
    if (wid == 0) {
        int w = (lane < 8) ? wsum[lane] : 0;
#pragma unroll
        for (int d = 1; d < 8; d <<= 1) {
            int t = __shfl_up_sync(0xffffffff, w, d);
            if (lane >= d) w += t;
        }
        if (lane < 8) wsum[lane] = w;
    }
    __syncthreads();
    int excl = inc - tot + (wid ? wsum[wid - 1] : 0);
    if (base + 0 < nseg) g_off[base + 0] = excl;
    if (base + 1 < nseg) g_off[base + 1] = excl + v0;
    if (base + 2 < nseg) g_off[base + 2] = excl + v0 + v1;
    if (base + 3 < nseg) g_off[base + 3] = excl + v0 + v1 + v2;
    if (tid == 255) g_bsum[blockIdx.x] = wsum[7];
}
__global__ void k_scan2(int nb) {
    __shared__ int sm[1024];
    int tid = threadIdx.x;
    int v = (tid < nb) ? g_bsum[tid] : 0;
    sm[tid] = v;
    __syncthreads();
    for (int d = 1; d < 1024; d <<= 1) {
        int t = (tid >= d) ? sm[tid - d] : 0;
        __syncthreads();
        sm[tid] += t;
        __syncthreads();
    }
    if (tid < nb) g_bsum[tid] = sm[tid] - v;
}
__global__ void k_scan3(int nseg) {
    int i = blockIdx.x * blockDim.x + threadIdx.x;
    if (i < nseg) {
        int v = g_off[i] + g_bsum[i >> 10];
        g_cur[i] = v;
        g_offcnt[i] = make_int2(v, g_cnt[i]);
    }
}
__global__ void k_scatter(const int* __restrict__ ei, const int* __restrict__ et, int E) {
    int e = blockIdx.x * blockDim.x + threadIdx.x;
    if (e >= E) return;
    int s = ei[E + e] * RNUM + et[e];
    int p = atomicAdd(&g_cur[s], 1);
    g_esrc[p] = ei[e];
}
__global__ void k_buildBf(const float* __restrict__ rel_w,
                          const float* __restrict__ root_w) {
    int idx = blockIdx.x * blockDim.x + threadIdx.x;
    if (idx >= NCHK * 8 * 4 * 32) return;
    int lane = idx & 31;
    int s = (idx >> 5) & 3;
    int j = (idx >> 7) & 7;
    int chunk = idx >> 10;
    uint32_t hi[4], lo[4];
#pragma unroll
    for (int q = 0; q < 4; q++) {
        int n = j * 16 + ((q & 2) ? 8 : 0) + (lane >> 2);
        int kk = s * 16 + ((q & 1) ? 8 : 0) + 2 * (lane & 3);
        float w0, w1;
        if (chunk < 14) {
            int r = chunk >> 1, kb = (chunk & 1) * 64;
            const float* p = rel_w + ((size_t)(r * CDIM + n)) * CDIM + kb + kk;
            w0 = p[0]; w1 = p[1];
        } else {
            int rc = chunk - 14;
            int t = rc >> 1, kb = (rc & 1) * 64;
            const float* p = root_w + ((size_t)(t * CDIM + n)) * CDIM + kb + kk;
            w0 = p[0]; w1 = p[1];
        }
        __nv_bfloat16 h0 = __float2bfloat16(w0), h1 = __float2bfloat16(w1);
        float r0 = w0 - __bfloat162float(h0), r1 = w1 - __bfloat162float(h1);
        hi[q] = (uint32_t)__bfloat16_as_ushort(h0) | ((uint32_t)__bfloat16_as_ushort(h1) << 16);
        lo[q] = packbf(r0, r1);
    }
    size_t base = ((((size_t)chunk * 8 + j) * 4 + s) * 2) * 32 + lane;
    g_Bf[base]      = make_uint4(hi[0], hi[1], hi[2], hi[3]);
    g_Bf[base + 32] = make_uint4(lo[0], lo[1], lo[2], lo[3]);
}

// ---------------- fused: pipelined gather + GEMM ----------------------------
// offcnt for 7 relations lives in registers (lane = phmod*8 + row),
// first-4 esrc indices double-buffered in registers across phases.
__global__ __launch_bounds__(512, 1) void k_fused(const float* __restrict__ x,
                                                  const int* __restrict__ tnt,
                                                  const float* __restrict__ root_b,
                                                  float* __restrict__ out, int Nn) {
    extern __shared__ char smem[];
    const uint32_t sb = smem_u32(smem);
    const int tid = threadIdx.x, wid = tid >> 5, lane = tid & 31;
    const int row0 = blockIdx.x * 128;
    const int wm0 = (wid & 7) * 16;
    const int jbase = (wid >> 3) * 4;
    const int wn0 = jbase * 16;
    const int quad = lane >> 3, lrow = lane & 7;
    const int a_roff = ((quad & 1) * 8 + lrow) * SROW + ((quad >> 1) * 8) * 2;
    const float4* x4 = reinterpret_cast<const float4*>(x);

    float acc[8][4];
#pragma unroll
    for (int j = 0; j < 8; j++)
#pragma unroll
        for (int q = 0; q < 4; q++) acc[j][q] = 0.f;

    // ---- preload per-warp metadata into registers ----
    // slot A: phase = lane>>3 (0..3), row = lane&7 ; slot B: phase = 4+(lane>>3) (4..6)
    int offA = 0, cntA = 0, offB = 0, cntB = 0, mytype = -1;
    {
        const int prow = lane & 7, pph = lane >> 3;
        const int dst = row0 + wid * 8 + prow;
        if (dst < Nn) {
            int2 a = g_offcnt[dst * RNUM + pph];
            offA = a.x; cntA = a.y;
            if (pph + 4 < RNUM) {
                int2 b = g_offcnt[dst * RNUM + pph + 4];
                offB = b.x; cntB = b.y;
            }
            if (lane < 8) mytype = tnt[dst];
        }
    }

    // prefetch B phase 0
    {
        const uint4* src = g_Bf;
        const uint32_t d0 = sb + SM_B;
#pragma unroll
        for (int i = 0; i < 8; i++)
            cp16(d0 + (tid + i * 512) * 16, src + tid + i * 512);
        CP_COMMIT();
    }

    // esrc prefetch for phase 0: lane -> (row = lane>>2, j = lane&3)
    int esrc_cur;
    {
        const int i = lane >> 2, j = lane & 3;
        const int sl = i;                         // phase 0 lives in slot A, pph=0
        int off = __shfl_sync(0xffffffffu, offA, sl);
        int cnt = __shfl_sync(0xffffffffu, cntA, sl);
        esrc_cur = (j < cnt) ? __ldg(&g_esrc[off + j]) : 0;
    }

    for (int phase = 0; phase < NPH; ++phase) {
        __syncthreads();   // prior mma done reading A + prior B stage free
        // ---- prefetch B for next phase ----
        if (phase + 1 < NPH) {
            const uint4* src = g_Bf + (size_t)(phase + 1) * 4096;
            const uint32_t d0 = sb + SM_B + ((phase + 1) & 1) * BSTAGE;
#pragma unroll
            for (int i = 0; i < 8; i++)
                cp16(d0 + (tid + i * 512) * 16, src + tid + i * 512);
        }
        CP_COMMIT();

        // ---- build A (8 rows per warp) ----
        if (phase < RNUM) {
            const bool slotA = (phase < 4);
            const int phm = phase & 3;
#pragma unroll
            for (int i = 0; i < 8; i++) {
                const int sl = (phm << 3) | i;
                const int cnt = __shfl_sync(0xffffffffu, slotA ? cntA : cntB, sl);
                const int off = __shfl_sync(0xffffffffu, slotA ? offA : offB, sl);
                const int s0 = __shfl_sync(0xffffffffu, esrc_cur, 4 * i + 0);
                const int s1 = __shfl_sync(0xffffffffu, esrc_cur, 4 * i + 1);
                const int s2 = __shfl_sync(0xffffffffu, esrc_cur, 4 * i + 2);
                const int s3 = __shfl_sync(0xffffffffu, esrc_cur, 4 * i + 3);
                float4 a = make_float4(0.f, 0.f, 0.f, 0.f);
                if (cnt > 0) { float4 u = x4[(size_t)s0 * 32 + lane];
                               a.x += u.x; a.y += u.y; a.z += u.z; a.w += u.w; }
                if (cnt > 1) { float4 u = x4[(size_t)s1 * 32 + lane];
                               a.x += u.x; a.y += u.y; a.z += u.z; a.w += u.w; }
                if (cnt > 2) { float4 u = x4[(size_t)s2 * 32 + lane];
                               a.x += u.x; a.y += u.y; a.z += u.z; a.w += u.w; }
                if (cnt > 3) { float4 u = x4[(size_t)s3 * 32 + lane];
                               a.x += u.x; a.y += u.y; a.z += u.z; a.w += u.w; }
                // rare tail (cnt > 4)
                for (int j = 4; j < cnt; j++) {
                    float4 u = x4[(size_t)__ldg(&g_esrc[off + j]) * 32 + lane];
                    a.x += u.x; a.y += u.y; a.z += u.z; a.w += u.w;
                }
                const float inv = 1.f / fmaxf((float)cnt, 1.f);
                a.x *= inv; a.y *= inv; a.z *= inv; a.w *= inv;
                storeA(sb, wid * 8 + i, lane, a);
            }
        } else {
            const int t = phase - RNUM;
#pragma unroll
            for (int i = 0; i < 8; i++) {
                const int ty = __shfl_sync(0xffffffffu, mytype, i);
                const int dst = row0 + wid * 8 + i;
                float4 v = make_float4(0.f, 0.f, 0.f, 0.f);
                if (ty == t) v = x4[(size_t)dst * 32 + lane];
                storeA(sb, wid * 8 + i, lane, v);
            }
        }
        // ---- prefetch esrc for next relation phase (flies during mma) ----
        if (phase + 1 < RNUM) {
            const int np = phase + 1;
            const bool slotA = (np < 4);
            const int i = lane >> 2, j = lane & 3;
            const int sl = ((np & 3) << 3) | i;
            int off = __shfl_sync(0xffffffffu, slotA ? offA : offB, sl);
            int cnt = __shfl_sync(0xffffffffu, slotA ? cntA : cntB, sl);
            esrc_cur = (j < cnt) ? __ldg(&g_esrc[off + j]) : 0;
        }

        CP_WAIT1();        // current phase's B landed
        __syncthreads();
        // ---- GEMM: 2 K-chunks of 64, B from SMEM ----
        const uint32_t sbB = sb + SM_B + (phase & 1) * BSTAGE;
#pragma unroll
        for (int cc = 0; cc < 2; cc++) {
#pragma unroll
            for (int s = 0; s < 4; s++) {
                uint32_t ah[4], al[4];
                const uint32_t abase = (uint32_t)wm0 * SROW + s * 32 + a_roff;
                ldmat_x4(sb + (cc * 2 + 0) * ATB + abase, ah);
                ldmat_x4(sb + (cc * 2 + 1) * ATB + abase, al);
#pragma unroll
                for (int jp = 0; jp < 4; jp++) {
                    const uint32_t boff = sbB +
                        ((((uint32_t)(cc * 8 + jbase + jp) * 4 + s) * 2) * 32 + lane) * 16;
                    uint4 BH = lds128(boff);
                    uint4 BL = lds128(boff + 512);
                    mma4(acc[2 * jp],     ah, BH.x, BH.y);
                    mma4(acc[2 * jp + 1], ah, BH.z, BH.w);
                    mma4(acc[2 * jp],     ah, BL.x, BL.y);
                    mma4(acc[2 * jp + 1], ah, BL.z, BL.w);
                    mma4(acc[2 * jp],     al, BH.x, BH.y);
                    mma4(acc[2 * jp + 1], al, BH.z, BH.w);
                }
            }
        }
    }

    // ---- epilogue: + root_b[tnt], single store ----
    const int g = lane >> 2, tig = lane & 3;
    const int r1 = row0 + wm0 + g;
    const int r2 = r1 + 8;
    const int t1 = (r1 < Nn) ? tnt[r1] : 0;
    const int t2 = (r2 < Nn) ? tnt[r2] : 0;
#pragma unroll
    for (int nt = 0; nt < 8; nt++) {
        const int col = wn0 + nt * 8 + tig * 2;
        if (r1 < Nn) {
            float2 b1 = *reinterpret_cast<const float2*>(root_b + t1 * CDIM + col);
            *reinterpret_cast<float2*>(out + (size_t)r1 * CDIM + col) =
                make_float2(acc[nt][0] + b1.x, acc[nt][1] + b1.y);
        }
        if (r2 < Nn) {
            float2 b2 = *reinterpret_cast<const float2*>(root_b + t2 * CDIM + col);
            *reinterpret_cast<float2*>(out + (size_t)r2 * CDIM + col) =
                make_float2(acc[nt][2] + b2.x, acc[nt][3] + b2.y);
        }
    }
}

// ---------------------------------------------------------------------------
extern "C" void kernel_launch(void* const* d_in, const int* in_sizes, int n_in,
                              void* d_out, int out_size) {
    const float* x      = (const float*)d_in[0];
    const int*   ei     = (const int*)d_in[1];
    const int*   et     = (const int*)d_in[2];
    const int*   tnt    = (const int*)d_in[3];
    const float* rel_w  = (const float*)d_in[4];
    const float* root_w = (const float*)d_in[5];
    const float* root_b = (const float*)d_in[6];
    float* out = (float*)d_out;

    int E  = in_sizes[2];
    int Nn = in_sizes[3];
    int nseg = Nn * RNUM;
    int nb = (nseg + 1023) / 1024;

    cudaFuncSetAttribute(k_fused, cudaFuncAttributeMaxDynamicSharedMemorySize, SM_TOT);

    k_zero<<<(nseg + 255) / 256, 256>>>(nseg);
    k_count<<<(E + 255) / 256, 256>>>(ei, et, E);
    k_scan1<<<nb, 256>>>(nseg);
    k_scan2<<<1, 1024>>>(nb);
    k_scan3<<<(nseg + 255) / 256, 256>>>(nseg);
    k_scatter<<<(E + 255) / 256, 256>>>(ei, et, E);
    k_buildBf<<<(NCHK * 8 * 4 * 32 + 255) / 256, 256>>>(rel_w, root_w);
    k_fused<<<(Nn + 127) / 128, 512, SM_TOT>>>(x, tnt, root_b, out, Nn);
}

// round 9
// speedup vs baseline: 1.9127x; 1.3991x over previous
#include <cuda_runtime.h>
#include <cuda_fp16.h>
#include <cstdint>

#define CDIM 128
#define RNUM 7
#define TNUM 4
#define MAXN 100000
#define MAXE 2000000
#define NPH  (RNUM + TNUM)           /* 11 phases */
#define NCHK 22
#define SROW 144                     /* padded smem row stride bytes */
#define ATB  (128 * SROW)            /* 18432 B per chunk buffer */
#define SM_B (2 * ATB)               /* B stages after A: 36864 */
#define BSTAGE 32768                 /* one B stage: 32 KB */
#define SM_TOT (SM_B + 2 * BSTAGE)   /* 102400 */

// ---------------- device scratch ----------------
__device__ int  g_cnt[MAXN * RNUM];
__device__ int  g_off[MAXN * RNUM];
__device__ int  g_cur[MAXN * RNUM];
__device__ int2 g_offcnt[MAXN * RNUM];
__device__ int  g_bsum[1024];
__device__ int  g_esrc[MAXE];
// B fragments (fp16): [chunk][j(8)][s(4)][lane(32)] uint4
__device__ __align__(16) uint4 g_Bf[NCHK * 8 * 4 * 32];

// ---------------- helpers ----------------
__device__ __forceinline__ uint32_t smem_u32(const void* p) {
    uint32_t a;
    asm("{ .reg .u64 t; cvta.to.shared.u64 t, %1; cvt.u32.u64 %0, t; }" : "=r"(a) : "l"(p));
    return a;
}
__device__ __forceinline__ void ldmat_x4(uint32_t addr, uint32_t* r) {
    asm volatile("ldmatrix.sync.aligned.m8n8.x4.shared.b16 {%0,%1,%2,%3}, [%4];"
                 : "=r"(r[0]), "=r"(r[1]), "=r"(r[2]), "=r"(r[3]) : "r"(addr));
}
__device__ __forceinline__ void mma4(float* d, const uint32_t* a, uint32_t b0, uint32_t b1) {
    asm volatile("mma.sync.aligned.m16n8k16.row.col.f32.f16.f16.f32 "
                 "{%0,%1,%2,%3}, {%4,%5,%6,%7}, {%8,%9}, {%0,%1,%2,%3};"
                 : "+f"(d[0]), "+f"(d[1]), "+f"(d[2]), "+f"(d[3])
                 : "r"(a[0]), "r"(a[1]), "r"(a[2]), "r"(a[3]), "r"(b0), "r"(b1));
}
__device__ __forceinline__ uint32_t packh(float a, float b) {
    __half2 h = __floats2half2_rn(a, b);
    return *reinterpret_cast<uint32_t*>(&h);
}
__device__ __forceinline__ uint4 lds128(uint32_t addr) {
    uint4 v;
    asm volatile("ld.shared.v4.b32 {%0,%1,%2,%3}, [%4];"
                 : "=r"(v.x), "=r"(v.y), "=r"(v.z), "=r"(v.w) : "r"(addr));
    return v;
}
__device__ __forceinline__ void cp16(uint32_t s, const void* g) {
    asm volatile("cp.async.cg.shared.global [%0], [%1], 16;" :: "r"(s), "l"(g));
}
#define CP_COMMIT() asm volatile("cp.async.commit_group;" ::: "memory")
#define CP_WAIT1()  asm volatile("cp.async.wait_group 1;" ::: "memory")

// store one float4 (4 k-values) of row m as fp16 into A buffers
__device__ __forceinline__ void storeA(uint32_t sbase, int m, int lane, float4 v) {
    int chunk = lane >> 4;
    uint32_t boff = (uint32_t)m * SROW + (lane & 15) * 8;
    uint32_t hp0 = packh(v.x, v.y), hp1 = packh(v.z, v.w);
    asm volatile("st.shared.v2.b32 [%0], {%1,%2};"
                 :: "r"(sbase + chunk * ATB + boff), "r"(hp0), "r"(hp1) : "memory");
}

// ---------------- prologue kernels ----------------
__global__ void k_zero(int nseg) {
    int i = blockIdx.x * blockDim.x + threadIdx.x;
    if (i < nseg) g_cnt[i] = 0;
}
__global__ void k_count(const int* __restrict__ ei, const int* __restrict__ et, int E) {
    int e = blockIdx.x * blockDim.x + threadIdx.x;
    if (e >= E) return;
    atomicAdd(&g_cnt[ei[E + e] * RNUM + et[e]], 1);
}
__global__ void k_scan1(int nseg) {
    __shared__ int wsum[8];
    int tid = threadIdx.x;
    int base = blockIdx.x * 1024 + tid * 4;
    int v0 = 0, v1 = 0, v2 = 0, v3 = 0;
    if (base + 0 < nseg) v0 = g_cnt[base + 0];
    if (base + 1 < nseg) v1 = g_cnt[base + 1];
    if (base + 2 < nseg) v2 = g_cnt[base + 2];
    if (base + 3 < nseg) v3 = g_cnt[base + 3];
    int tot = v0 + v1 + v2 + v3;
    int lane = tid & 31, wid = tid >> 5;
    int inc = tot;
#pragma unroll
    for (int d = 1; d < 32; d <<= 1) {
        int t = __shfl_up_sync(0xffffffff, inc, d);
        if (lane >= d) inc += t;
    }
    if (lane == 31) wsum[wid] = inc;
    __syncthreads();
    if (wid == 0) {
        int w = (lane < 8) ? wsum[lane] : 0;
#pragma unroll
        for (int d = 1; d < 8; d <<= 1) {
            int t = __shfl_up_sync(0xffffffff, w, d);
            if (lane >= d) w += t;
        }
        if (lane < 8) wsum[lane] = w;
    }
    __syncthreads();
    int excl = inc - tot + (wid ? wsum[wid - 1] : 0);
    if (base + 0 < nseg) g_off[base + 0] = excl;
    if (base + 1 < nseg) g_off[base + 1] = excl + v0;
    if (base + 2 < nseg) g_off[base + 2] = excl + v0 + v1;
    if (base + 3 < nseg) g_off[base + 3] = excl + v0 + v1 + v2;
    if (tid == 255) g_bsum[blockIdx.x] = wsum[7];
}
__global__ void k_scan2(int nb) {
    __shared__ int sm[1024];
    int tid = threadIdx.x;
    int v = (tid < nb) ? g_bsum[tid] : 0;
    sm[tid] = v;
    __syncthreads();
    for (int d = 1; d < 1024; d <<= 1) {
        int t = (tid >= d) ? sm[tid - d] : 0;
        __syncthreads();
        sm[tid] += t;
        __syncthreads();
    }
    if (tid < nb) g_bsum[tid] = sm[tid] - v;
}
__global__ void k_scan3(int nseg) {
    int i = blockIdx.x * blockDim.x + threadIdx.x;
    if (i < nseg) {
        int v = g_off[i] + g_bsum[i >> 10];
        g_cur[i] = v;
        g_offcnt[i] = make_int2(v, g_cnt[i]);
    }
}
__global__ void k_scatter(const int* __restrict__ ei, const int* __restrict__ et, int E) {
    int e = blockIdx.x * blockDim.x + threadIdx.x;
    if (e >= E) return;
    int s = ei[E + e] * RNUM + et[e];
    int p = atomicAdd(&g_cur[s], 1);
    g_esrc[p] = ei[e];
}
__global__ void k_buildBf(const float* __restrict__ rel_w,
                          const float* __restrict__ root_w) {
    int idx = blockIdx.x * blockDim.x + threadIdx.x;
    if (idx >= NCHK * 8 * 4 * 32) return;
    int lane = idx & 31;
    int s = (idx >> 5) & 3;
    int j = (idx >> 7) & 7;
    int chunk = idx >> 10;
    uint32_t hq[4];
#pragma unroll
    for (int q = 0; q < 4; q++) {
        int n = j * 16 + ((q & 2) ? 8 : 0) + (lane >> 2);
        int kk = s * 16 + ((q & 1) ? 8 : 0) + 2 * (lane & 3);
        float w0, w1;
        if (chunk < 14) {
            int r = chunk >> 1, kb = (chunk & 1) * 64;
            const float* p = rel_w + ((size_t)(r * CDIM + n)) * CDIM + kb + kk;
            w0 = p[0]; w1 = p[1];
        } else {
            int rc = chunk - 14;
            int t = rc >> 1, kb = (rc & 1) * 64;
            const float* p = root_w + ((size_t)(t * CDIM + n)) * CDIM + kb + kk;
            w0 = p[0]; w1 = p[1];
        }
        hq[q] = packh(w0, w1);
    }
    g_Bf[(((size_t)chunk * 8 + j) * 4 + s) * 32 + lane] =
        make_uint4(hq[0], hq[1], hq[2], hq[3]);
}

// ---------------- fused: pipelined gather + single-term fp16 GEMM ----------
__global__ __launch_bounds__(512, 1) void k_fused(const float* __restrict__ x,
                                                  const int* __restrict__ tnt,
                                                  const float* __restrict__ root_b,
                                                  float* __restrict__ out, int Nn) {
    extern __shared__ char smem[];
    const uint32_t sb = smem_u32(smem);
    const int tid = threadIdx.x, wid = tid >> 5, lane = tid & 31;
    const int row0 = blockIdx.x * 128;
    const int wm0 = (wid & 7) * 16;
    const int jbase = (wid >> 3) * 4;
    const int wn0 = jbase * 16;
    const int quad = lane >> 3, lrow = lane & 7;
    const int a_roff = ((quad & 1) * 8 + lrow) * SROW + ((quad >> 1) * 8) * 2;
    const float4* x4 = reinterpret_cast<const float4*>(x);

    float acc[8][4];
#pragma unroll
    for (int j = 0; j < 8; j++)
#pragma unroll
        for (int q = 0; q < 4; q++) acc[j][q] = 0.f;

    // ---- preload per-warp metadata into registers ----
    int offA = 0, cntA = 0, offB = 0, cntB = 0, mytype = -1;
    {
        const int prow = lane & 7, pph = lane >> 3;
        const int dst = row0 + wid * 8 + prow;
        if (dst < Nn) {
            int2 a = g_offcnt[dst * RNUM + pph];
            offA = a.x; cntA = a.y;
            if (pph + 4 < RNUM) {
                int2 b = g_offcnt[dst * RNUM + pph + 4];
                offB = b.x; cntB = b.y;
            }
            if (lane < 8) mytype = tnt[dst];
        }
    }

    // prefetch B phase 0 (2048 uint4 = 32 KB)
    {
        const uint4* src = g_Bf;
        const uint32_t d0 = sb + SM_B;
#pragma unroll
        for (int i = 0; i < 4; i++)
            cp16(d0 + (tid + i * 512) * 16, src + tid + i * 512);
        CP_COMMIT();
    }

    // esrc prefetch for phase 0
    int esrc_cur;
    {
        const int i = lane >> 2, j = lane & 3;
        int off = __shfl_sync(0xffffffffu, offA, i);
        int cnt = __shfl_sync(0xffffffffu, cntA, i);
        esrc_cur = (j < cnt) ? __ldg(&g_esrc[off + j]) : 0;
    }

    for (int phase = 0; phase < NPH; ++phase) {
        __syncthreads();
        // ---- prefetch B for next phase ----
        if (phase + 1 < NPH) {
            const uint4* src = g_Bf + (size_t)(phase + 1) * 2048;
            const uint32_t d0 = sb + SM_B + ((phase + 1) & 1) * BSTAGE;
#pragma unroll
            for (int i = 0; i < 4; i++)
                cp16(d0 + (tid + i * 512) * 16, src + tid + i * 512);
        }
        CP_COMMIT();

        // ---- build A (8 rows per warp) ----
        if (phase < RNUM) {
            const bool slotA = (phase < 4);
            const int phm = phase & 3;
#pragma unroll
            for (int i = 0; i < 8; i++) {
                const int sl = (phm << 3) | i;
                const int cnt = __shfl_sync(0xffffffffu, slotA ? cntA : cntB, sl);
                const int off = __shfl_sync(0xffffffffu, slotA ? offA : offB, sl);
                const int s0 = __shfl_sync(0xffffffffu, esrc_cur, 4 * i + 0);
                const int s1 = __shfl_sync(0xffffffffu, esrc_cur, 4 * i + 1);
                const int s2 = __shfl_sync(0xffffffffu, esrc_cur, 4 * i + 2);
                const int s3 = __shfl_sync(0xffffffffu, esrc_cur, 4 * i + 3);
                float4 a = make_float4(0.f, 0.f, 0.f, 0.f);
                if (cnt > 0) { float4 u = x4[(size_t)s0 * 32 + lane];
                               a.x += u.x; a.y += u.y; a.z += u.z; a.w += u.w; }
                if (cnt > 1) { float4 u = x4[(size_t)s1 * 32 + lane];
                               a.x += u.x; a.y += u.y; a.z += u.z; a.w += u.w; }
                if (cnt > 2) { float4 u = x4[(size_t)s2 * 32 + lane];
                               a.x += u.x; a.y += u.y; a.z += u.z; a.w += u.w; }
                if (cnt > 3) { float4 u = x4[(size_t)s3 * 32 + lane];
                               a.x += u.x; a.y += u.y; a.z += u.z; a.w += u.w; }
                for (int j = 4; j < cnt; j++) {
                    float4 u = x4[(size_t)__ldg(&g_esrc[off + j]) * 32 + lane];
                    a.x += u.x; a.y += u.y; a.z += u.z; a.w += u.w;
                }
                const float inv = 1.f / fmaxf((float)cnt, 1.f);
                a.x *= inv; a.y *= inv; a.z *= inv; a.w *= inv;
                storeA(sb, wid * 8 + i, lane, a);
            }
        } else {
            const int t = phase - RNUM;
#pragma unroll
            for (int i = 0; i < 8; i++) {
                const int ty = __shfl_sync(0xffffffffu, mytype, i);
                const int dst = row0 + wid * 8 + i;
                float4 v = make_float4(0.f, 0.f, 0.f, 0.f);
                if (ty == t) v = x4[(size_t)dst * 32 + lane];
                storeA(sb, wid * 8 + i, lane, v);
            }
        }
        // ---- prefetch esrc for next relation phase ----
        if (phase + 1 < RNUM) {
            const int np = phase + 1;
            const bool slotA = (np < 4);
            const int i = lane >> 2, j = lane & 3;
            const int sl = ((np & 3) << 3) | i;
            int off = __shfl_sync(0xffffffffu, slotA ? offA : offB, sl);
            int cnt = __shfl_sync(0xffffffffu, slotA ? cntA : cntB, sl);
            esrc_cur = (j < cnt) ? __ldg(&g_esrc[off + j]) : 0;
        }

        CP_WAIT1();
        __syncthreads();
        // ---- GEMM: 2 K-chunks of 64, fp16 single term ----
        const uint32_t sbB = sb + SM_B + (phase & 1) * BSTAGE;
#pragma unroll
        for (int cc = 0; cc < 2; cc++) {
#pragma unroll
            for (int s = 0; s < 4; s++) {
                uint32_t ah[4];
                const uint32_t abase = (uint32_t)wm0 * SROW + s * 32 + a_roff;
                ldmat_x4(sb + cc * ATB + abase, ah);
#pragma unroll
                for (int jp = 0; jp < 4; jp++) {
                    const uint32_t boff = sbB +
                        ((uint32_t)cc * 1024 + ((jbase + jp) * 4 + s) * 32 + lane) * 16;
                    uint4 BH = lds128(boff);
                    mma4(acc[2 * jp],     ah, BH.x, BH.y);
                    mma4(acc[2 * jp + 1], ah, BH.z, BH.w);
                }
            }
        }
    }

    // ---- epilogue: + root_b[tnt], single store ----
    const int g = lane >> 2, tig = lane & 3;
    const int r1 = row0 + wm0 + g;
    const int r2 = r1 + 8;
    const int t1 = (r1 < Nn) ? tnt[r1] : 0;
    const int t2 = (r2 < Nn) ? tnt[r2] : 0;
#pragma unroll
    for (int nt = 0; nt < 8; nt++) {
        const int col = wn0 + nt * 8 + tig * 2;
        if (r1 < Nn) {
            float2 b1 = *reinterpret_cast<const float2*>(root_b + t1 * CDIM + col);
            *reinterpret_cast<float2*>(out + (size_t)r1 * CDIM + col) =
                make_float2(acc[nt][0] + b1.x, acc[nt][1] + b1.y);
        }
        if (r2 < Nn) {
            float2 b2 = *reinterpret_cast<const float2*>(root_b + t2 * CDIM + col);
            *reinterpret_cast<float2*>(out + (size_t)r2 * CDIM + col) =
                make_float2(acc[nt][2] + b2.x, acc[nt][3] + b2.y);
        }
    }
}

// ---------------------------------------------------------------------------
extern "C" void kernel_launch(void* const* d_in, const int* in_sizes, int n_in,
                              void* d_out, int out_size) {
    const float* x      = (const float*)d_in[0];
    const int*   ei     = (const int*)d_in[1];
    const int*   et     = (const int*)d_in[2];
    const int*   tnt    = (const int*)d_in[3];
    const float* rel_w  = (const float*)d_in[4];
    const float* root_w = (const float*)d_in[5];
    const float* root_b = (const float*)d_in[6];
    float* out = (float*)d_out;

    int E  = in_sizes[2];
    int Nn = in_sizes[3];
    int nseg = Nn * RNUM;
    int nb = (nseg + 1023) / 1024;

    cudaFuncSetAttribute(k_fused, cudaFuncAttributeMaxDynamicSharedMemorySize, SM_TOT);

    k_zero<<<(nseg + 255) / 256, 256>>>(nseg);
    k_count<<<(E + 255) / 256, 256>>>(ei, et, E);
    k_scan1<<<nb, 256>>>(nseg);
    k_scan2<<<1, 1024>>>(nb);
    k_scan3<<<(nseg + 255) / 256, 256>>>(nseg);
    k_scatter<<<(E + 255) / 256, 256>>>(ei, et, E);
    k_buildBf<<<(NCHK * 8 * 4 * 32 + 255) / 256, 256>>>(rel_w, root_w);
    k_fused<<<(Nn + 127) / 128, 512, SM_TOT>>>(x, tnt, root_b, out, Nn);
}

// round 10
// speedup vs baseline: 2.2586x; 1.1809x over previous
#include <cuda_runtime.h>
#include <cuda_fp16.h>
#include <cstdint>

#define CDIM 128
#define RNUM 7
#define TNUM 4
#define MAXN 100000
#define MAXE 2000000
#define NPH  (RNUM + TNUM)           /* 11 phases */
#define NCHK 22
#define SROW 144                     /* padded smem row stride bytes */
#define ATB  (128 * SROW)            /* 18432 B per chunk buffer */
#define SM_B (2 * ATB)               /* B stages after A: 36864 */
#define BSTAGE 32768                 /* one B stage: 32 KB */
#define SM_TOT (SM_B + 2 * BSTAGE)   /* 102400 per CTA -> 2 CTAs/SM */

// ---------------- device scratch ----------------
__device__ int  g_cnt[MAXN * RNUM];
__device__ int  g_off[MAXN * RNUM];
__device__ int  g_cur[MAXN * RNUM];
__device__ int2 g_offcnt[MAXN * RNUM];
__device__ int  g_bsum[1024];
__device__ int  g_esrc[MAXE];
// B fragments (fp16): [chunk][j(8)][s(4)][lane(32)] uint4
__device__ __align__(16) uint4 g_Bf[NCHK * 8 * 4 * 32];

// ---------------- helpers ----------------
__device__ __forceinline__ uint32_t smem_u32(const void* p) {
    uint32_t a;
    asm("{ .reg .u64 t; cvta.to.shared.u64 t, %1; cvt.u32.u64 %0, t; }" : "=r"(a) : "l"(p));
    return a;
}
__device__ __forceinline__ void ldmat_x4(uint32_t addr, uint32_t* r) {
    asm volatile("ldmatrix.sync.aligned.m8n8.x4.shared.b16 {%0,%1,%2,%3}, [%4];"
                 : "=r"(r[0]), "=r"(r[1]), "=r"(r[2]), "=r"(r[3]) : "r"(addr));
}
__device__ __forceinline__ void mma4(float* d, const uint32_t* a, uint32_t b0, uint32_t b1) {
    asm volatile("mma.sync.aligned.m16n8k16.row.col.f32.f16.f16.f32 "
                 "{%0,%1,%2,%3}, {%4,%5,%6,%7}, {%8,%9}, {%0,%1,%2,%3};"
                 : "+f"(d[0]), "+f"(d[1]), "+f"(d[2]), "+f"(d[3])
                 : "r"(a[0]), "r"(a[1]), "r"(a[2]), "r"(a[3]), "r"(b0), "r"(b1));
}
__device__ __forceinline__ uint32_t packh(float a, float b) {
    __half2 h = __floats2half2_rn(a, b);
    return *reinterpret_cast<uint32_t*>(&h);
}
__device__ __forceinline__ uint4 lds128(uint32_t addr) {
    uint4 v;
    asm volatile("ld.shared.v4.b32 {%0,%1,%2,%3}, [%4];"
                 : "=r"(v.x), "=r"(v.y), "=r"(v.z), "=r"(v.w) : "r"(addr));
    return v;
}
__device__ __forceinline__ void cp16(uint32_t s, const void* g) {
    asm volatile("cp.async.cg.shared.global [%0], [%1], 16;" :: "r"(s), "l"(g));
}
#define CP_COMMIT() asm volatile("cp.async.commit_group;" ::: "memory")
#define CP_WAIT1()  asm volatile("cp.async.wait_group 1;" ::: "memory")

// select one of 4 scalars by runtime index (uniform across warp)
__device__ __forceinline__ int sel4(int s, int a0, int a1, int a2, int a3) {
    int lo = (s & 1) ? a1 : a0;
    int hi = (s & 1) ? a3 : a2;
    return (s & 2) ? hi : lo;
}

// store one float4 (4 k-values) of row m as fp16 into A buffers
__device__ __forceinline__ void storeA(uint32_t sbase, int m, int lane, float4 v) {
    int chunk = lane >> 4;
    uint32_t boff = (uint32_t)m * SROW + (lane & 15) * 8;
    uint32_t hp0 = packh(v.x, v.y), hp1 = packh(v.z, v.w);
    asm volatile("st.shared.v2.b32 [%0], {%1,%2};"
                 :: "r"(sbase + chunk * ATB + boff), "r"(hp0), "r"(hp1) : "memory");
}

// ---------------- prologue kernels (unchanged) ----------------
__global__ void k_zero(int nseg) {
    int i = blockIdx.x * blockDim.x + threadIdx.x;
    if (i < nseg) g_cnt[i] = 0;
}
__global__ void k_count(const int* __restrict__ ei, const int* __restrict__ et, int E) {
    int e = blockIdx.x * blockDim.x + threadIdx.x;
    if (e >= E) return;
    atomicAdd(&g_cnt[ei[E + e] * RNUM + et[e]], 1);
}
__global__ void k_scan1(int nseg) {
    __shared__ int wsum[8];
    int tid = threadIdx.x;
    int base = blockIdx.x * 1024 + tid * 4;
    int v0 = 0, v1 = 0, v2 = 0, v3 = 0;
    if (base + 0 < nseg) v0 = g_cnt[base + 0];
    if (base + 1 < nseg) v1 = g_cnt[base + 1];
    if (base + 2 < nseg) v2 = g_cnt[base + 2];
    if (base + 3 < nseg) v3 = g_cnt[base + 3];
    int tot = v0 + v1 + v2 + v3;
    int lane = tid & 31, wid = tid >> 5;
    int inc = tot;
#pragma unroll
    for (int d = 1; d < 32; d <<= 1) {
        int t = __shfl_up_sync(0xffffffff, inc, d);
        if (lane >= d) inc += t;
    }
    if (lane == 31) wsum[wid] = inc;
    __syncthreads();
    if (wid == 0) {
        int w = (lane < 8) ? wsum[lane] : 0;
#pragma unroll
        for (int d = 1; d < 8; d <<= 1) {
            int t = __shfl_up_sync(0xffffffff, w, d);
            if (lane >= d) w += t;
        }
        if (lane < 8) wsum[lane] = w;
    }
    __syncthreads();
    int excl = inc - tot + (wid ? wsum[wid - 1] : 0);
    if (base + 0 < nseg) g_off[base + 0] = excl;
    if (base + 1 < nseg) g_off[base + 1] = excl + v0;
    if (base + 2 < nseg) g_off[base + 2] = excl + v0 + v1;
    if (base + 3 < nseg) g_off[base + 3] = excl + v0 + v1 + v2;
    if (tid == 255) g_bsum[blockIdx.x] = wsum[7];
}
__global__ void k_scan2(int nb) {
    __shared__ int sm[1024];
    int tid = threadIdx.x;
    int v = (tid < nb) ? g_bsum[tid] : 0;
    sm[tid] = v;
    __syncthreads();
    for (int d = 1; d < 1024; d <<= 1) {
        int t = (tid >= d) ? sm[tid - d] : 0;
        __syncthreads();
        sm[tid] += t;
        __syncthreads();
    }
    if (tid < nb) g_bsum[tid] = sm[tid] - v;
}
__global__ void k_scan3(int nseg) {
    int i = blockIdx.x * blockDim.x + threadIdx.x;
    if (i < nseg) {
        int v = g_off[i] + g_bsum[i >> 10];
        g_cur[i] = v;
        g_offcnt[i] = make_int2(v, g_cnt[i]);
    }
}
__global__ void k_scatter(const int* __restrict__ ei, const int* __restrict__ et, int E) {
    int e = blockIdx.x * blockDim.x + threadIdx.x;
    if (e >= E) return;
    int s = ei[E + e] * RNUM + et[e];
    int p = atomicAdd(&g_cur[s], 1);
    g_esrc[p] = ei[e];
}
__global__ void k_buildBf(const float* __restrict__ rel_w,
                          const float* __restrict__ root_w) {
    int idx = blockIdx.x * blockDim.x + threadIdx.x;
    if (idx >= NCHK * 8 * 4 * 32) return;
    int lane = idx & 31;
    int s = (idx >> 5) & 3;
    int j = (idx >> 7) & 7;
    int chunk = idx >> 10;
    uint32_t hq[4];
#pragma unroll
    for (int q = 0; q < 4; q++) {
        int n = j * 16 + ((q & 2) ? 8 : 0) + (lane >> 2);
        int kk = s * 16 + ((q & 1) ? 8 : 0) + 2 * (lane & 3);
        float w0, w1;
        if (chunk < 14) {
            int r = chunk >> 1, kb = (chunk & 1) * 64;
            const float* p = rel_w + ((size_t)(r * CDIM + n)) * CDIM + kb + kk;
            w0 = p[0]; w1 = p[1];
        } else {
            int rc = chunk - 14;
            int t = rc >> 1, kb = (rc & 1) * 64;
            const float* p = root_w + ((size_t)(t * CDIM + n)) * CDIM + kb + kk;
            w0 = p[0]; w1 = p[1];
        }
        hq[q] = packh(w0, w1);
    }
    g_Bf[(((size_t)chunk * 8 + j) * 4 + s) * 32 + lane] =
        make_uint4(hq[0], hq[1], hq[2], hq[3]);
}

// ---------------- fused: 256 threads, 2 CTAs/SM ------------------------------
// 8 warps: warp tile 32x64 (wm0 = (wid&3)*32, wn0 = (wid>>2)*64), acc 64 regs.
// A-build: warp owns rows wid*16..wid*16+15.
// metadata: 4 slot regs, slot k holds phases 2k,2k+1 at lane = (ph&1)*16+row.
__global__ __launch_bounds__(256, 2) void k_fused(const float* __restrict__ x,
                                                  const int* __restrict__ tnt,
                                                  const float* __restrict__ root_b,
                                                  float* __restrict__ out, int Nn) {
    extern __shared__ char smem[];
    const uint32_t sb = smem_u32(smem);
    const int tid = threadIdx.x, wid = tid >> 5, lane = tid & 31;
    const int row0 = blockIdx.x * 128;
    const int wm0 = (wid & 3) * 32;
    const int jbase = (wid >> 2) * 4;
    const int wn0 = jbase * 16;
    const int quad = lane >> 3, lrow = lane & 7;
    const int a_roff = ((quad & 1) * 8 + lrow) * SROW + ((quad >> 1) * 8) * 2;
    const float4* x4 = reinterpret_cast<const float4*>(x);

    float acc[16][4];
#pragma unroll
    for (int j = 0; j < 16; j++)
#pragma unroll
        for (int q = 0; q < 4; q++) acc[j][q] = 0.f;

    // ---- metadata preload: slot k covers phases 2k (lanes 0-15) and 2k+1 (16-31)
    int off_s0 = 0, cnt_s0 = 0, off_s1 = 0, cnt_s1 = 0;
    int off_s2 = 0, cnt_s2 = 0, off_s3 = 0, cnt_s3 = 0;
    int mytype = -1;
    {
        const int prow = lane & 15;
        const int pdst = row0 + wid * 16 + prow;
        const int ppar = lane >> 4;
        if (pdst < Nn) {
            { int2 a = g_offcnt[pdst * RNUM + (0 + ppar)]; off_s0 = a.x; cnt_s0 = a.y; }
            { int2 a = g_offcnt[pdst * RNUM + (2 + ppar)]; off_s1 = a.x; cnt_s1 = a.y; }
            { int2 a = g_offcnt[pdst * RNUM + (4 + ppar)]; off_s2 = a.x; cnt_s2 = a.y; }
            if (ppar == 0) { int2 a = g_offcnt[pdst * RNUM + 6]; off_s3 = a.x; cnt_s3 = a.y; }
            if (lane < 16) mytype = tnt[pdst];
        }
    }

    // prefetch B phase 0 (2048 uint4 = 32 KB over 256 threads)
    {
        const uint4* src = g_Bf;
        const uint32_t d0 = sb + SM_B;
#pragma unroll
        for (int i = 0; i < 8; i++)
            cp16(d0 + (tid + i * 256) * 16, src + tid + i * 256);
        CP_COMMIT();
    }

    // esrc prefetch for phase 0: esrcA rows 0-7 (lane=row*4+j), esrcB rows 8-15
    int esrcA, esrcB;
    {
        const int r = lane >> 2, j = lane & 3;
        int offp = off_s0, cntp = cnt_s0;   // phase 0 -> slot0, par 0 (lanes 0-15)
        int offa = __shfl_sync(0xffffffffu, offp, r);
        int cnta = __shfl_sync(0xffffffffu, cntp, r);
        esrcA = (j < cnta) ? __ldg(&g_esrc[offa + j]) : 0;
        int offb = __shfl_sync(0xffffffffu, offp, 8 + r);
        int cntb = __shfl_sync(0xffffffffu, cntp, 8 + r);
        esrcB = (j < cntb) ? __ldg(&g_esrc[offb + j]) : 0;
    }

    for (int phase = 0; phase < NPH; ++phase) {
        __syncthreads();
        // ---- prefetch B for next phase ----
        if (phase + 1 < NPH) {
            const uint4* src = g_Bf + (size_t)(phase + 1) * 2048;
            const uint32_t d0 = sb + SM_B + ((phase + 1) & 1) * BSTAGE;
#pragma unroll
            for (int i = 0; i < 8; i++)
                cp16(d0 + (tid + i * 256) * 16, src + tid + i * 256);
        }
        CP_COMMIT();

        // ---- build A (16 rows per warp) ----
        if (phase < RNUM) {
            const int slot = phase >> 1;
            const int par = (phase & 1) * 16;
            const int offp = sel4(slot, off_s0, off_s1, off_s2, off_s3);
            const int cntp = sel4(slot, cnt_s0, cnt_s1, cnt_s2, cnt_s3);
#pragma unroll
            for (int i = 0; i < 16; i++) {
                const int cnt = __shfl_sync(0xffffffffu, cntp, par + i);
                const int off = __shfl_sync(0xffffffffu, offp, par + i);
                const int src01 = (i < 8) ? esrcA : esrcB;
                const int ib = (i & 7) * 4;
                const int s0 = __shfl_sync(0xffffffffu, src01, ib + 0);
                const int s1 = __shfl_sync(0xffffffffu, src01, ib + 1);
                const int s2 = __shfl_sync(0xffffffffu, src01, ib + 2);
                const int s3 = __shfl_sync(0xffffffffu, src01, ib + 3);
                float4 a = make_float4(0.f, 0.f, 0.f, 0.f);
                if (cnt > 0) { float4 u = x4[(size_t)s0 * 32 + lane];
                               a.x += u.x; a.y += u.y; a.z += u.z; a.w += u.w; }
                if (cnt > 1) { float4 u = x4[(size_t)s1 * 32 + lane];
                               a.x += u.x; a.y += u.y; a.z += u.z; a.w += u.w; }
                if (cnt > 2) { float4 u = x4[(size_t)s2 * 32 + lane];
                               a.x += u.x; a.y += u.y; a.z += u.z; a.w += u.w; }
                if (cnt > 3) { float4 u = x4[(size_t)s3 * 32 + lane];
                               a.x += u.x; a.y += u.y; a.z += u.z; a.w += u.w; }
                for (int j = 4; j < cnt; j++) {
                    float4 u = x4[(size_t)__ldg(&g_esrc[off + j]) * 32 + lane];
                    a.x += u.x; a.y += u.y; a.z += u.z; a.w += u.w;
                }
                const float inv = 1.f / fmaxf((float)cnt, 1.f);
                a.x *= inv; a.y *= inv; a.z *= inv; a.w *= inv;
                storeA(sb, wid * 16 + i, lane, a);
            }
        } else {
            const int t = phase - RNUM;
#pragma unroll
            for (int i = 0; i < 16; i++) {
                const int ty = __shfl_sync(0xffffffffu, mytype, i);
                const int dst = row0 + wid * 16 + i;
                float4 v = make_float4(0.f, 0.f, 0.f, 0.f);
                if (ty == t) v = x4[(size_t)dst * 32 + lane];
                storeA(sb, wid * 16 + i, lane, v);
            }
        }
        // ---- prefetch esrc for next relation phase ----
        if (phase + 1 < RNUM) {
            const int np = phase + 1;
            const int slot = np >> 1;
            const int par = (np & 1) * 16;
            const int offp = sel4(slot, off_s0, off_s1, off_s2, off_s3);
            const int cntp = sel4(slot, cnt_s0, cnt_s1, cnt_s2, cnt_s3);
            const int r = lane >> 2, j = lane & 3;
            int offa = __shfl_sync(0xffffffffu, offp, par + r);
            int cnta = __shfl_sync(0xffffffffu, cntp, par + r);
            esrcA = (j < cnta) ? __ldg(&g_esrc[offa + j]) : 0;
            int offb = __shfl_sync(0xffffffffu, offp, par + 8 + r);
            int cntb = __shfl_sync(0xffffffffu, cntp, par + 8 + r);
            esrcB = (j < cntb) ? __ldg(&g_esrc[offb + j]) : 0;
        }

        CP_WAIT1();
        __syncthreads();
        // ---- GEMM: warp tile 32x64, 2 K-chunks of 64 ----
        const uint32_t sbB = sb + SM_B + (phase & 1) * BSTAGE;
#pragma unroll
        for (int cc = 0; cc < 2; cc++) {
#pragma unroll
            for (int s = 0; s < 4; s++) {
                uint32_t ah0[4], ah1[4];
                const uint32_t ab0 = sb + cc * ATB + (uint32_t)wm0 * SROW + s * 32 + a_roff;
                ldmat_x4(ab0, ah0);
                ldmat_x4(ab0 + 16 * SROW, ah1);
#pragma unroll
                for (int jp = 0; jp < 4; jp++) {
                    const uint32_t boff = sbB +
                        ((uint32_t)cc * 1024 + ((jbase + jp) * 4 + s) * 32 + lane) * 16;
                    uint4 BH = lds128(boff);
                    mma4(acc[2 * jp],         ah0, BH.x, BH.y);
                    mma4(acc[2 * jp + 1],     ah0, BH.z, BH.w);
                    mma4(acc[8 + 2 * jp],     ah1, BH.x, BH.y);
                    mma4(acc[8 + 2 * jp + 1], ah1, BH.z, BH.w);
                }
            }
        }
    }

    // ---- epilogue: + root_b[tnt], single store ----
    const int g = lane >> 2, tig = lane & 3;
#pragma unroll
    for (int ms = 0; ms < 2; ms++) {
        const int r1 = row0 + wm0 + ms * 16 + g;
        const int r2 = r1 + 8;
        const int t1 = (r1 < Nn) ? tnt[r1] : 0;
        const int t2 = (r2 < Nn) ? tnt[r2] : 0;
#pragma unroll
        for (int nt = 0; nt < 8; nt++) {
            const int col = wn0 + nt * 8 + tig * 2;
            if (r1 < Nn) {
                float2 b1 = *reinterpret_cast<const float2*>(root_b + t1 * CDIM + col);
                *reinterpret_cast<float2*>(out + (size_t)r1 * CDIM + col) =
                    make_float2(acc[ms * 8 + nt][0] + b1.x, acc[ms * 8 + nt][1] + b1.y);
            }
            if (r2 < Nn) {
                float2 b2 = *reinterpret_cast<const float2*>(root_b + t2 * CDIM + col);
                *reinterpret_cast<float2*>(out + (size_t)r2 * CDIM + col) =
                    make_float2(acc[ms * 8 + nt][2] + b2.x, acc[ms * 8 + nt][3] + b2.y);
            }
        }
    }
}

// ---------------------------------------------------------------------------
extern "C" void kernel_launch(void* const* d_in, const int* in_sizes, int n_in,
                              void* d_out, int out_size) {
    const float* x      = (const float*)d_in[0];
    const int*   ei     = (const int*)d_in[1];
    const int*   et     = (const int*)d_in[2];
    const int*   tnt    = (const int*)d_in[3];
    const float* rel_w  = (const float*)d_in[4];
    const float* root_w = (const float*)d_in[5];
    const float* root_b = (const float*)d_in[6];
    float* out = (float*)d_out;

    int E  = in_sizes[2];
    int Nn = in_sizes[3];
    int nseg = Nn * RNUM;
    int nb = (nseg + 1023) / 1024;

    cudaFuncSetAttribute(k_fused, cudaFuncAttributeMaxDynamicSharedMemorySize, SM_TOT);

    k_zero<<<(nseg + 255) / 256, 256>>>(nseg);
    k_count<<<(E + 255) / 256, 256>>>(ei, et, E);
    k_scan1<<<nb, 256>>>(nseg);
    k_scan2<<<1, 1024>>>(nb);
    k_scan3<<<(nseg + 255) / 256, 256>>>(nseg);
    k_scatter<<<(E + 255) / 256, 256>>>(ei, et, E);
    k_buildBf<<<(NCHK * 8 * 4 * 32 + 255) / 256, 256>>>(rel_w, root_w);
    k_fused<<<(Nn + 127) / 128, 256, SM_TOT>>>(x, tnt, root_b, out, Nn);
}

// round 11
// speedup vs baseline: 2.3395x; 1.0358x over previous
#include <cuda_runtime.h>
#include <cuda_fp16.h>
#include <cstdint>

#define CDIM 128
#define RNUM 7
#define TNUM 4
#define MAXN 100000
#define MAXE 2000000
#define NPH  (RNUM + TNUM)           /* 11 phases max */
#define NCHK 22
#define SROW 144                     /* padded smem row stride bytes */
#define ATB  (128 * SROW)            /* 18432 B per chunk buffer */
#define SM_B (2 * ATB)               /* B stages after A: 36864 */
#define BSTAGE 32768                 /* one B stage: 32 KB */
#define SM_ACT (SM_B + 2 * BSTAGE)   /* 102400: mask/nact/act list */
#define SM_TOT (SM_ACT + 64)         /* 102464 per CTA -> 2 CTAs/SM */

// ---------------- device scratch ----------------
__device__ int  g_cnt[MAXN * RNUM];
__device__ int  g_off[MAXN * RNUM];
__device__ int  g_cur[MAXN * RNUM];
__device__ int2 g_offcnt[MAXN * RNUM];
__device__ int  g_bsum[1024];
__device__ int  g_esrc[MAXE];
__device__ int  g_tcnt[4], g_tcur[4];
__device__ int  g_perm[MAXN];
// B fragments (fp16): [chunk][j(8)][s(4)][lane(32)] uint4
__device__ __align__(16) uint4 g_Bf[NCHK * 8 * 4 * 32];

// ---------------- helpers ----------------
__device__ __forceinline__ uint32_t smem_u32(const void* p) {
    uint32_t a;
    asm("{ .reg .u64 t; cvta.to.shared.u64 t, %1; cvt.u32.u64 %0, t; }" : "=r"(a) : "l"(p));
    return a;
}
__device__ __forceinline__ void ldmat_x4(uint32_t addr, uint32_t* r) {
    asm volatile("ldmatrix.sync.aligned.m8n8.x4.shared.b16 {%0,%1,%2,%3}, [%4];"
                 : "=r"(r[0]), "=r"(r[1]), "=r"(r[2]), "=r"(r[3]) : "r"(addr));
}
__device__ __forceinline__ void mma4(float* d, const uint32_t* a, uint32_t b0, uint32_t b1) {
    asm volatile("mma.sync.aligned.m16n8k16.row.col.f32.f16.f16.f32 "
                 "{%0,%1,%2,%3}, {%4,%5,%6,%7}, {%8,%9}, {%0,%1,%2,%3};"
                 : "+f"(d[0]), "+f"(d[1]), "+f"(d[2]), "+f"(d[3])
                 : "r"(a[0]), "r"(a[1]), "r"(a[2]), "r"(a[3]), "r"(b0), "r"(b1));
}
__device__ __forceinline__ uint32_t packh(float a, float b) {
    __half2 h = __floats2half2_rn(a, b);
    return *reinterpret_cast<uint32_t*>(&h);
}
__device__ __forceinline__ uint4 lds128(uint32_t addr) {
    uint4 v;
    asm volatile("ld.shared.v4.b32 {%0,%1,%2,%3}, [%4];"
                 : "=r"(v.x), "=r"(v.y), "=r"(v.z), "=r"(v.w) : "r"(addr));
    return v;
}
__device__ __forceinline__ void cp16(uint32_t s, const void* g) {
    asm volatile("cp.async.cg.shared.global [%0], [%1], 16;" :: "r"(s), "l"(g));
}
#define CP_COMMIT() asm volatile("cp.async.commit_group;" ::: "memory")
#define CP_WAIT1()  asm volatile("cp.async.wait_group 1;" ::: "memory")

__device__ __forceinline__ int sel4(int s, int a0, int a1, int a2, int a3) {
    int lo = (s & 1) ? a1 : a0;
    int hi = (s & 1) ? a3 : a2;
    return (s & 2) ? hi : lo;
}
__device__ __forceinline__ void storeA(uint32_t sbase, int m, int lane, float4 v) {
    int chunk = lane >> 4;
    uint32_t boff = (uint32_t)m * SROW + (lane & 15) * 8;
    uint32_t hp0 = packh(v.x, v.y), hp1 = packh(v.z, v.w);
    asm volatile("st.shared.v2.b32 [%0], {%1,%2};"
                 :: "r"(sbase + chunk * ATB + boff), "r"(hp0), "r"(hp1) : "memory");
}

// ---------------- prologue kernels ----------------
__global__ void k_zero(int nseg) {
    int i = blockIdx.x * blockDim.x + threadIdx.x;
    if (i < nseg) g_cnt[i] = 0;
    if (i < 4) g_tcnt[i] = 0;
}
__global__ void k_count(const int* __restrict__ ei, const int* __restrict__ et, int E) {
    int e = blockIdx.x * blockDim.x + threadIdx.x;
    if (e >= E) return;
    atomicAdd(&g_cnt[ei[E + e] * RNUM + et[e]], 1);
}
__global__ void k_scan1(int nseg) {
    __shared__ int wsum[8];
    int tid = threadIdx.x;
    int base = blockIdx.x * 1024 + tid * 4;
    int v0 = 0, v1 = 0, v2 = 0, v3 = 0;
    if (base + 0 < nseg) v0 = g_cnt[base + 0];
    if (base + 1 < nseg) v1 = g_cnt[base + 1];
    if (base + 2 < nseg) v2 = g_cnt[base + 2];
    if (base + 3 < nseg) v3 = g_cnt[base + 3];
    int tot = v0 + v1 + v2 + v3;
    int lane = tid & 31, wid = tid >> 5;
    int inc = tot;
#pragma unroll
    for (int d = 1; d < 32; d <<= 1) {
        int t = __shfl_up_sync(0xffffffff, inc, d);
        if (lane >= d) inc += t;
    }
    if (lane == 31) wsum[wid] = inc;
    __syncthreads();
    if (wid == 0) {
        int w = (lane < 8) ? wsum[lane] : 0;
#pragma unroll
        for (int d = 1; d < 8; d <<= 1) {
            int t = __shfl_up_sync(0xffffffff, w, d);
            if (lane >= d) w += t;
        }
        if (lane < 8) wsum[lane] = w;
    }
    __syncthreads();
    int excl = inc - tot + (wid ? wsum[wid - 1] : 0);
    if (base + 0 < nseg) g_off[base + 0] = excl;
    if (base + 1 < nseg) g_off[base + 1] = excl + v0;
    if (base + 2 < nseg) g_off[base + 2] = excl + v0 + v1;
    if (base + 3 < nseg) g_off[base + 3] = excl + v0 + v1 + v2;
    if (tid == 255) g_bsum[blockIdx.x] = wsum[7];
}
__global__ void k_scan2(int nb) {
    __shared__ int sm[1024];
    int tid = threadIdx.x;
    int v = (tid < nb) ? g_bsum[tid] : 0;
    sm[tid] = v;
    __syncthreads();
    for (int d = 1; d < 1024; d <<= 1) {
        int t = (tid >= d) ? sm[tid - d] : 0;
        __syncthreads();
        sm[tid] += t;
        __syncthreads();
    }
    if (tid < nb) g_bsum[tid] = sm[tid] - v;
}
__global__ void k_scan3(int nseg) {
    int i = blockIdx.x * blockDim.x + threadIdx.x;
    if (i < nseg) {
        int v = g_off[i] + g_bsum[i >> 10];
        g_cur[i] = v;
        g_offcnt[i] = make_int2(v, g_cnt[i]);
    }
}
__global__ void k_scatter(const int* __restrict__ ei, const int* __restrict__ et, int E) {
    int e = blockIdx.x * blockDim.x + threadIdx.x;
    if (e >= E) return;
    int s = ei[E + e] * RNUM + et[e];
    int p = atomicAdd(&g_cur[s], 1);
    g_esrc[p] = ei[e];
}
// ---- counting sort of nodes by type ----
__global__ void k_tcount(const int* __restrict__ tnt, int Nn) {
    __shared__ int h[4];
    if (threadIdx.x < 4) h[threadIdx.x] = 0;
    __syncthreads();
    int i = blockIdx.x * blockDim.x + threadIdx.x;
    if (i < Nn) atomicAdd(&h[tnt[i]], 1);
    __syncthreads();
    if (threadIdx.x < 4) atomicAdd(&g_tcnt[threadIdx.x], h[threadIdx.x]);
}
__global__ void k_tscan() {
    if (threadIdx.x == 0) {
        int a = g_tcnt[0], b = g_tcnt[1], c = g_tcnt[2];
        g_tcur[0] = 0; g_tcur[1] = a; g_tcur[2] = a + b; g_tcur[3] = a + b + c;
    }
}
__global__ void k_tscatter(const int* __restrict__ tnt, int Nn) {
    __shared__ int loc[4], base[4];
    if (threadIdx.x < 4) loc[threadIdx.x] = 0;
    __syncthreads();
    int i = blockIdx.x * blockDim.x + threadIdx.x;
    int t = 0, my = 0;
    bool ok = (i < Nn);
    if (ok) { t = tnt[i]; my = atomicAdd(&loc[t], 1); }
    __syncthreads();
    if (threadIdx.x < 4) base[threadIdx.x] = atomicAdd(&g_tcur[threadIdx.x], loc[threadIdx.x]);
    __syncthreads();
    if (ok) g_perm[base[t] + my] = i;
}
__global__ void k_buildBf(const float* __restrict__ rel_w,
                          const float* __restrict__ root_w) {
    int idx = blockIdx.x * blockDim.x + threadIdx.x;
    if (idx >= NCHK * 8 * 4 * 32) return;
    int lane = idx & 31;
    int s = (idx >> 5) & 3;
    int j = (idx >> 7) & 7;
    int chunk = idx >> 10;
    uint32_t hq[4];
#pragma unroll
    for (int q = 0; q < 4; q++) {
        int n = j * 16 + ((q & 2) ? 8 : 0) + (lane >> 2);
        int kk = s * 16 + ((q & 1) ? 8 : 0) + 2 * (lane & 3);
        float w0, w1;
        if (chunk < 14) {
            int r = chunk >> 1, kb = (chunk & 1) * 64;
            const float* p = rel_w + ((size_t)(r * CDIM + n)) * CDIM + kb + kk;
            w0 = p[0]; w1 = p[1];
        } else {
            int rc = chunk - 14;
            int t = rc >> 1, kb = (rc & 1) * 64;
            const float* p = root_w + ((size_t)(t * CDIM + n)) * CDIM + kb + kk;
            w0 = p[0]; w1 = p[1];
        }
        hq[q] = packh(w0, w1);
    }
    g_Bf[(((size_t)chunk * 8 + j) * 4 + s) * 32 + lane] =
        make_uint4(hq[0], hq[1], hq[2], hq[3]);
}

// ---------------- fused: 256 threads, 2 CTAs/SM, active-phase list ----------
__global__ __launch_bounds__(256, 2) void k_fused(const float* __restrict__ x,
                                                  const int* __restrict__ tnt,
                                                  const float* __restrict__ root_b,
                                                  float* __restrict__ out, int Nn) {
    extern __shared__ char smem[];
    const uint32_t sb = smem_u32(smem);
    int* s_act = reinterpret_cast<int*>(smem + SM_ACT); // [0]=mask, [1]=nact, [2..]=list
    const int tid = threadIdx.x, wid = tid >> 5, lane = tid & 31;
    const int row0 = blockIdx.x * 128;
    const int wm0 = (wid & 3) * 32;
    const int jbase = (wid >> 2) * 4;
    const int wn0 = jbase * 16;
    const int quad = lane >> 3, lrow = lane & 7;
    const int a_roff = ((quad & 1) * 8 + lrow) * SROW + ((quad >> 1) * 8) * 2;
    const float4* x4 = reinterpret_cast<const float4*>(x);

    float acc[16][4];
#pragma unroll
    for (int j = 0; j < 16; j++)
#pragma unroll
        for (int q = 0; q < 4; q++) acc[j][q] = 0.f;

    if (tid == 0) s_act[0] = 0;
    __syncthreads();

    // ---- metadata preload (via perm): slot k covers phases 2k (lanes 0-15), 2k+1 (16-31)
    int off_s0 = 0, cnt_s0 = 0, off_s1 = 0, cnt_s1 = 0;
    int off_s2 = 0, cnt_s2 = 0, off_s3 = 0, cnt_s3 = 0;
    int mytype = -1, pdstReg = 0;
    {
        const int prow = lane & 15;
        const int grow = row0 + wid * 16 + prow;
        const int ppar = lane >> 4;
        if (grow < Nn) {
            const int pd = g_perm[grow];
            { int2 a = g_offcnt[pd * RNUM + (0 + ppar)]; off_s0 = a.x; cnt_s0 = a.y; }
            { int2 a = g_offcnt[pd * RNUM + (2 + ppar)]; off_s1 = a.x; cnt_s1 = a.y; }
            { int2 a = g_offcnt[pd * RNUM + (4 + ppar)]; off_s2 = a.x; cnt_s2 = a.y; }
            if (ppar == 0) { int2 a = g_offcnt[pd * RNUM + 6]; off_s3 = a.x; cnt_s3 = a.y; }
            if (lane < 16) {
                pdstReg = pd;
                mytype = tnt[pd];
                atomicOr(&s_act[0], 1 << mytype);
            }
        }
    }
    __syncthreads();
    if (tid == 0) {
        const int m = s_act[0];
        int n = 0;
#pragma unroll
        for (int p = 0; p < RNUM; p++) s_act[2 + n++] = p;
#pragma unroll
        for (int t = 0; t < TNUM; t++)
            if (m & (1 << t)) s_act[2 + n++] = RNUM + t;
        s_act[1] = n;
    }
    __syncthreads();
    const int nact = s_act[1];

    // prefetch B phase 0 (always relation 0)
    {
        const uint4* src = g_Bf;
        const uint32_t d0 = sb + SM_B;
#pragma unroll
        for (int i = 0; i < 8; i++)
            cp16(d0 + (tid + i * 256) * 16, src + tid + i * 256);
        CP_COMMIT();
    }

    // esrc prefetch for phase 0
    int esrcA, esrcB;
    {
        const int r = lane >> 2, j = lane & 3;
        int offa = __shfl_sync(0xffffffffu, off_s0, r);
        int cnta = __shfl_sync(0xffffffffu, cnt_s0, r);
        esrcA = (j < cnta) ? __ldg(&g_esrc[offa + j]) : 0;
        int offb = __shfl_sync(0xffffffffu, off_s0, 8 + r);
        int cntb = __shfl_sync(0xffffffffu, cnt_s0, 8 + r);
        esrcB = (j < cntb) ? __ldg(&g_esrc[offb + j]) : 0;
    }

    for (int ip = 0; ip < nact; ++ip) {
        const int phase = s_act[2 + ip];
        __syncthreads();
        // ---- prefetch B for next active phase ----
        if (ip + 1 < nact) {
            const uint4* src = g_Bf + (size_t)s_act[2 + ip + 1] * 2048;
            const uint32_t d0 = sb + SM_B + ((ip + 1) & 1) * BSTAGE;
#pragma unroll
            for (int i = 0; i < 8; i++)
                cp16(d0 + (tid + i * 256) * 16, src + tid + i * 256);
        }
        CP_COMMIT();

        // ---- build A (16 rows per warp) ----
        if (phase < RNUM) {
            const int slot = phase >> 1;
            const int par = (phase & 1) * 16;
            const int offp = sel4(slot, off_s0, off_s1, off_s2, off_s3);
            const int cntp = sel4(slot, cnt_s0, cnt_s1, cnt_s2, cnt_s3);
#pragma unroll
            for (int i = 0; i < 16; i++) {
                const int cnt = __shfl_sync(0xffffffffu, cntp, par + i);
                const int off = __shfl_sync(0xffffffffu, offp, par + i);
                const int src01 = (i < 8) ? esrcA : esrcB;
                const int ib = (i & 7) * 4;
                const int s0 = __shfl_sync(0xffffffffu, src01, ib + 0);
                const int s1 = __shfl_sync(0xffffffffu, src01, ib + 1);
                const int s2 = __shfl_sync(0xffffffffu, src01, ib + 2);
                const int s3 = __shfl_sync(0xffffffffu, src01, ib + 3);
                float4 a = make_float4(0.f, 0.f, 0.f, 0.f);
                if (cnt > 0) { float4 u = x4[(size_t)s0 * 32 + lane];
                               a.x += u.x; a.y += u.y; a.z += u.z; a.w += u.w; }
                if (cnt > 1) { float4 u = x4[(size_t)s1 * 32 + lane];
                               a.x += u.x; a.y += u.y; a.z += u.z; a.w += u.w; }
                if (cnt > 2) { float4 u = x4[(size_t)s2 * 32 + lane];
                               a.x += u.x; a.y += u.y; a.z += u.z; a.w += u.w; }
                if (cnt > 3) { float4 u = x4[(size_t)s3 * 32 + lane];
                               a.x += u.x; a.y += u.y; a.z += u.z; a.w += u.w; }
                for (int j = 4; j < cnt; j++) {
                    float4 u = x4[(size_t)__ldg(&g_esrc[off + j]) * 32 + lane];
                    a.x += u.x; a.y += u.y; a.z += u.z; a.w += u.w;
                }
                const float inv = 1.f / fmaxf((float)cnt, 1.f);
                a.x *= inv; a.y *= inv; a.z *= inv; a.w *= inv;
                storeA(sb, wid * 16 + i, lane, a);
            }
        } else {
            const int t = phase - RNUM;
#pragma unroll
            for (int i = 0; i < 16; i++) {
                const int ty = __shfl_sync(0xffffffffu, mytype, i);
                const int pdst = __shfl_sync(0xffffffffu, pdstReg, i);
                float4 v = make_float4(0.f, 0.f, 0.f, 0.f);
                if (ty == t) v = x4[(size_t)pdst * 32 + lane];
                storeA(sb, wid * 16 + i, lane, v);
            }
        }
        // ---- prefetch esrc for next relation phase ----
        if (phase + 1 < RNUM) {
            const int np = phase + 1;
            const int slot = np >> 1;
            const int par = (np & 1) * 16;
            const int offp = sel4(slot, off_s0, off_s1, off_s2, off_s3);
            const int cntp = sel4(slot, cnt_s0, cnt_s1, cnt_s2, cnt_s3);
            const int r = lane >> 2, j = lane & 3;
            int offa = __shfl_sync(0xffffffffu, offp, par + r);
            int cnta = __shfl_sync(0xffffffffu, cntp, par + r);
            esrcA = (j < cnta) ? __ldg(&g_esrc[offa + j]) : 0;
            int offb = __shfl_sync(0xffffffffu, offp, par + 8 + r);
            int cntb = __shfl_sync(0xffffffffu, cntp, par + 8 + r);
            esrcB = (j < cntb) ? __ldg(&g_esrc[offb + j]) : 0;
        }

        CP_WAIT1();
        __syncthreads();
        // ---- GEMM: warp tile 32x64, 2 K-chunks of 64 ----
        const uint32_t sbB = sb + SM_B + (ip & 1) * BSTAGE;
#pragma unroll
        for (int cc = 0; cc < 2; cc++) {
#pragma unroll
            for (int s = 0; s < 4; s++) {
                uint32_t ah0[4], ah1[4];
                const uint32_t ab0 = sb + cc * ATB + (uint32_t)wm0 * SROW + s * 32 + a_roff;
                ldmat_x4(ab0, ah0);
                ldmat_x4(ab0 + 16 * SROW, ah1);
#pragma unroll
                for (int jp = 0; jp < 4; jp++) {
                    const uint32_t boff = sbB +
                        ((uint32_t)cc * 1024 + ((jbase + jp) * 4 + s) * 32 + lane) * 16;
                    uint4 BH = lds128(boff);
                    mma4(acc[2 * jp],         ah0, BH.x, BH.y);
                    mma4(acc[2 * jp + 1],     ah0, BH.z, BH.w);
                    mma4(acc[8 + 2 * jp],     ah1, BH.x, BH.y);
                    mma4(acc[8 + 2 * jp + 1], ah1, BH.z, BH.w);
                }
            }
        }
    }

    // ---- epilogue: + root_b[tnt], store via perm ----
    const int g = lane >> 2, tig = lane & 3;
#pragma unroll
    for (int ms = 0; ms < 2; ms++) {
        const int gr1 = row0 + wm0 + ms * 16 + g;
        const int gr2 = gr1 + 8;
        const int n1 = (gr1 < Nn) ? g_perm[gr1] : 0;
        const int n2 = (gr2 < Nn) ? g_perm[gr2] : 0;
        const int t1 = (gr1 < Nn) ? tnt[n1] : 0;
        const int t2 = (gr2 < Nn) ? tnt[n2] : 0;
#pragma unroll
        for (int nt = 0; nt < 8; nt++) {
            const int col = wn0 + nt * 8 + tig * 2;
            if (gr1 < Nn) {
                float2 b1 = *reinterpret_cast<const float2*>(root_b + t1 * CDIM + col);
                *reinterpret_cast<float2*>(out + (size_t)n1 * CDIM + col) =
                    make_float2(acc[ms * 8 + nt][0] + b1.x, acc[ms * 8 + nt][1] + b1.y);
            }
            if (gr2 < Nn) {
                float2 b2 = *reinterpret_cast<const float2*>(root_b + t2 * CDIM + col);
                *reinterpret_cast<float2*>(out + (size_t)n2 * CDIM + col) =
                    make_float2(acc[ms * 8 + nt][2] + b2.x, acc[ms * 8 + nt][3] + b2.y);
            }
        }
    }
}

// ---------------------------------------------------------------------------
extern "C" void kernel_launch(void* const* d_in, const int* in_sizes, int n_in,
                              void* d_out, int out_size) {
    const float* x      = (const float*)d_in[0];
    const int*   ei     = (const int*)d_in[1];
    const int*   et     = (const int*)d_in[2];
    const int*   tnt    = (const int*)d_in[3];
    const float* rel_w  = (const float*)d_in[4];
    const float* root_w = (const float*)d_in[5];
    const float* root_b = (const float*)d_in[6];
    float* out = (float*)d_out;

    int E  = in_sizes[2];
    int Nn = in_sizes[3];
    int nseg = Nn * RNUM;
    int nb = (nseg + 1023) / 1024;

    cudaFuncSetAttribute(k_fused, cudaFuncAttributeMaxDynamicSharedMemorySize, SM_TOT);

    k_zero<<<(nseg + 255) / 256, 256>>>(nseg);
    k_count<<<(E + 255) / 256, 256>>>(ei, et, E);
    k_tcount<<<(Nn + 255) / 256, 256>>>(tnt, Nn);
    k_scan1<<<nb, 256>>>(nseg);
    k_scan2<<<1, 1024>>>(nb);
    k_tscan<<<1, 32>>>();
    k_scan3<<<(nseg + 255) / 256, 256>>>(nseg);
    k_scatter<<<(E + 255) / 256, 256>>>(ei, et, E);
    k_tscatter<<<(Nn + 255) / 256, 256>>>(tnt, Nn);
    k_buildBf<<<(NCHK * 8 * 4 * 32 + 255) / 256, 256>>>(rel_w, root_w);
    k_fused<<<(Nn + 127) / 128, 256, SM_TOT>>>(x, tnt, root_b, out, Nn);
}